// round 10
// baseline (speedup 1.0000x reference)
#include <cuda_runtime.h>
#include <math.h>
#include <stdint.h>

// Problem constants
#define BB    4
#define TSEQ  2048
#define CDIM  768
#define HEADS 12
#define HD    64
#define MLPD  3072
#define NTOK  (BB*TSEQ)          // 8192
#define QKVN  (3*CDIM)           // 2304

// ---------------------------------------------------------------------------
// Scratch (device globals; no allocation allowed)
// ---------------------------------------------------------------------------
__device__ float g_xn  [NTOK*CDIM];
__device__ float g_qkv [NTOK*QKVN];
__device__ float g_att [NTOK*CDIM];
__device__ float g_x2  [NTOK*CDIM];
__device__ float g_y   [NTOK*CDIM];
__device__ float g_h   [NTOK*MLPD];
__device__ float g_wqkv[CDIM*QKVN];

// ---------------------------------------------------------------------------
// Repack [H,C,D] x3 -> fused [C, 3*H*D]
// ---------------------------------------------------------------------------
__global__ void repackqkv_kernel(const float* __restrict__ wq,
                                 const float* __restrict__ wk,
                                 const float* __restrict__ wv,
                                 float* __restrict__ o) {
    int i = blockIdx.x * 256 + threadIdx.x;
    if (i >= HEADS * CDIM * HD) return;
    int h = i / (CDIM * HD);
    int r = i % (CDIM * HD);
    int c = r / HD;
    int d = r % HD;
    size_t base = (size_t)c * QKVN + h * HD + d;
    o[base]            = wq[i];
    o[base + CDIM]     = wk[i];
    o[base + 2*CDIM]   = wv[i];
}

// ---------------------------------------------------------------------------
// LayerNorm: one block per token row, 256 threads, C=768 -> 3 elems/thread
// ---------------------------------------------------------------------------
__global__ void ln_kernel(const float* __restrict__ x,
                          const float* __restrict__ g,
                          const float* __restrict__ b,
                          float* __restrict__ out) {
    int row = blockIdx.x;
    int tid = threadIdx.x;
    const float* xr = x + (size_t)row * CDIM;

    float v0 = xr[tid];
    float v1 = xr[tid + 256];
    float v2 = xr[tid + 512];
    float s  = v0 + v1 + v2;
    float s2 = v0*v0 + v1*v1 + v2*v2;

    #pragma unroll
    for (int o = 16; o > 0; o >>= 1) {
        s  += __shfl_xor_sync(0xffffffffu, s,  o);
        s2 += __shfl_xor_sync(0xffffffffu, s2, o);
    }
    __shared__ float rs[8], rs2[8];
    int w = tid >> 5, l = tid & 31;
    if (l == 0) { rs[w] = s; rs2[w] = s2; }
    __syncthreads();
    if (tid < 32) {
        float a  = (l < 8) ? rs[l]  : 0.f;
        float a2 = (l < 8) ? rs2[l] : 0.f;
        #pragma unroll
        for (int o = 4; o > 0; o >>= 1) {
            a  += __shfl_xor_sync(0xffffffffu, a,  o);
            a2 += __shfl_xor_sync(0xffffffffu, a2, o);
        }
        if (l == 0) { rs[0] = a; rs2[0] = a2; }
    }
    __syncthreads();
    float mu  = rs[0] * (1.f / CDIM);
    float var = rs2[0] * (1.f / CDIM) - mu * mu;
    float inv = rsqrtf(var + 1e-6f);

    float* orow = out + (size_t)row * CDIM;
    orow[tid]       = (v0 - mu) * inv * g[tid]       + b[tid];
    orow[tid + 256] = (v1 - mu) * inv * g[tid + 256] + b[tid + 256];
    orow[tid + 512] = (v2 - mu) * inv * g[tid + 512] + b[tid + 512];
}

// ---------------------------------------------------------------------------
// Common helpers
// ---------------------------------------------------------------------------
__device__ __forceinline__ float gelu_exact(float v) {
    return 0.5f * v * (1.0f + erff(v * 0.70710678118654752f));
}

__device__ __forceinline__ uint32_t f2tf32(float f) {
    uint32_t u;
    asm("cvt.rna.tf32.f32 %0, %1;" : "=r"(u) : "f"(f));
    return u;
}

#define MMA_TF32(d, a0,a1,a2,a3, b0,b1)                                      \
    asm volatile(                                                            \
        "mma.sync.aligned.m16n8k8.row.col.f32.tf32.tf32.f32 "                \
        "{%0,%1,%2,%3}, {%4,%5,%6,%7}, {%8,%9}, {%0,%1,%2,%3};"              \
        : "+f"(d[0]), "+f"(d[1]), "+f"(d[2]), "+f"(d[3])                     \
        : "r"(a0), "r"(a1), "r"(a2), "r"(a3), "r"(b0), "r"(b1))

__device__ __forceinline__ void cp16(float* dst_smem, const float* src_gmem) {
    uint32_t d = (uint32_t)__cvta_generic_to_shared(dst_smem);
    asm volatile("cp.async.cg.shared.global [%0], [%1], 16;\n"
                 :: "r"(d), "l"(src_gmem));
}
#define CP_COMMIT()  asm volatile("cp.async.commit_group;\n" ::: "memory")
#define CP_WAIT(n)   asm volatile("cp.async.wait_group %0;\n" :: "n"(n) : "memory")

// ---------------------------------------------------------------------------
// TF32 tensor-core GEMM v2: 3-stage cp.async pipeline.
// C = act(A[M,K] @ B[K,N] + bias) + res
// 128x128 tile, BK=32, 256 threads (8 warps 2x4), mma.m16n8k8.tf32.
// smem per stage: sA [128 m][36]  (stride 36 -> frag bank 4*gq+t4, bijective)
//                 sB [32 k][136]  (stride 136 -> frag bank 8*t4+gq, bijective)
// cp.async stores hit the conflict-free 4-phase floor on both tiles.
// mma consumes raw f32 bits (HW tf32 truncation) — no cvt in the hot loop.
// ---------------------------------------------------------------------------
#define AST 36
#define BST 136
#define STG_WORDS (128*AST + 32*BST)      // 8960 words = 35840 B
#define NSTAGE 3
#define GEMM_SMEM (NSTAGE*STG_WORDS*4)    // 107520 B

template<int ACT, int HASBIAS, int HASRES>
__global__ void __launch_bounds__(256, 2)
tgemm_kernel(const float* __restrict__ A, const float* __restrict__ B,
             const float* __restrict__ bias, const float* __restrict__ res,
             float* __restrict__ C, int M, int N, int K) {
    extern __shared__ float smg[];

    int tid  = threadIdx.x;
    int lane = tid & 31;
    int warp = tid >> 5;
    int wm = warp >> 2;            // 0..1 -> 64 rows each
    int wn = warp & 3;             // 0..3 -> 32 cols each
    int t4 = lane & 3;
    int gq = lane >> 2;
    int m0 = blockIdx.y * 128, n0 = blockIdx.x * 128;

    // A loader: thread covers row arow, k-half ap (4 x 16B chunks)
    int arow = tid >> 1;
    int ap   = tid & 1;
    const float* Ap = A + (size_t)(m0 + arow) * K + ap * 16;
    // B loader: thread covers k-row brow, col chunks bch + 32c
    int brow = tid >> 3;
    int bch  = (tid & 7) * 4;
    const float* Bp = B + (size_t)brow * N + n0 + bch;

    float acc[4][4][4];
    #pragma unroll
    for (int a = 0; a < 4; a++)
        #pragma unroll
        for (int b = 0; b < 4; b++)
            #pragma unroll
            for (int c = 0; c < 4; c++) acc[a][b][c] = 0.f;

    const int NK = K / 32;

    // prologue: issue stages 0..NSTAGE-2
    #pragma unroll
    for (int s = 0; s < NSTAGE - 1; s++) {
        float* sa = smg + s * STG_WORDS;
        float* sb = sa + 128 * AST;
        int k0 = s * 32;
        #pragma unroll
        for (int c = 0; c < 4; c++)
            cp16(&sa[arow * AST + ap * 16 + c * 4], Ap + k0 + c * 4);
        #pragma unroll
        for (int c = 0; c < 4; c++)
            cp16(&sb[brow * BST + bch + c * 32],
                 Bp + (size_t)k0 * N + c * 32);
        CP_COMMIT();
    }

    for (int i = 0; i < NK; i++) {
        CP_WAIT(NSTAGE - 2);
        __syncthreads();

        const uint32_t* sa = (const uint32_t*)(smg + (i % NSTAGE) * STG_WORDS);
        const uint32_t* sb = sa + 128 * AST;

        #pragma unroll
        for (int ks = 0; ks < 4; ks++) {
            int kb = ks * 8 + t4;
            uint32_t bf[4][2];
            #pragma unroll
            for (int nt = 0; nt < 4; nt++) {
                int gn = wn * 32 + nt * 8 + gq;
                bf[nt][0] = sb[kb * BST + gn];
                bf[nt][1] = sb[(kb + 4) * BST + gn];
            }
            uint32_t af[4][4];
            #pragma unroll
            for (int mt = 0; mt < 4; mt++) {
                int gm = wm * 64 + mt * 16 + gq;
                af[mt][0] = sa[gm * AST + kb];           // A[g][t4]
                af[mt][1] = sa[(gm + 8) * AST + kb];     // A[g+8][t4]
                af[mt][2] = sa[gm * AST + kb + 4];       // A[g][t4+4]
                af[mt][3] = sa[(gm + 8) * AST + kb + 4]; // A[g+8][t4+4]
            }
            #pragma unroll
            for (int mt = 0; mt < 4; mt++)
                #pragma unroll
                for (int nt = 0; nt < 4; nt++) {
                    float* d = acc[mt][nt];
                    MMA_TF32(d, af[mt][0], af[mt][1], af[mt][2], af[mt][3],
                             bf[nt][0], bf[nt][1]);
                }
        }

        // issue tile i+NSTAGE-1 (or empty group to keep wait counts valid)
        int nt_ = i + NSTAGE - 1;
        if (nt_ < NK) {
            float* sa_w = smg + (nt_ % NSTAGE) * STG_WORDS;
            float* sb_w = sa_w + 128 * AST;
            int k0 = nt_ * 32;
            #pragma unroll
            for (int c = 0; c < 4; c++)
                cp16(&sa_w[arow * AST + ap * 16 + c * 4], Ap + k0 + c * 4);
            #pragma unroll
            for (int c = 0; c < 4; c++)
                cp16(&sb_w[brow * BST + bch + c * 32],
                     Bp + (size_t)k0 * N + c * 32);
        }
        CP_COMMIT();
    }

    // Epilogue
    #pragma unroll
    for (int mt = 0; mt < 4; mt++) {
        int gr = m0 + wm * 64 + mt * 16 + gq;
        #pragma unroll
        for (int nt = 0; nt < 4; nt++) {
            int gc = n0 + wn * 32 + nt * 8 + t4 * 2;
            float2 v0, v1;
            v0.x = acc[mt][nt][0]; v0.y = acc[mt][nt][1];
            v1.x = acc[mt][nt][2]; v1.y = acc[mt][nt][3];
            if (HASBIAS) {
                float2 bb = *(const float2*)&bias[gc];
                v0.x += bb.x; v0.y += bb.y;
                v1.x += bb.x; v1.y += bb.y;
            }
            if (ACT == 1) {
                v0.x = gelu_exact(v0.x); v0.y = gelu_exact(v0.y);
                v1.x = gelu_exact(v1.x); v1.y = gelu_exact(v1.y);
            }
            if (HASRES) {
                float2 r0 = *(const float2*)&res[(size_t)gr * N + gc];
                float2 r1 = *(const float2*)&res[(size_t)(gr + 8) * N + gc];
                v0.x += r0.x; v0.y += r0.y;
                v1.x += r1.x; v1.y += r1.y;
            }
            *(float2*)&C[(size_t)gr * N + gc]       = v0;
            *(float2*)&C[(size_t)(gr + 8) * N + gc] = v1;
        }
    }
}

// ---------------------------------------------------------------------------
// Tensor-core flash attention v3: register-prefetched K/V tiles.
// Per (b,h): BR=128 query rows / block (8 warps x 16 rows), BC=64 kv tile.
// Dynamic smem (53.2KB): pk[64][136] (Q^T / K^T / P), sv[64][72] (V).
// ---------------------------------------------------------------------------
#define PKS 136
#define SVS 72
#define FLASH_SMEM ((64*PKS + 64*SVS) * 4)

__global__ void __launch_bounds__(256, 1)
flash_tc_kernel(const float* __restrict__ Q, const float* __restrict__ K,
                const float* __restrict__ V, float* __restrict__ O) {
    extern __shared__ uint32_t smf[];
    uint32_t* pk = smf;              // 64 * PKS
    uint32_t* sv = smf + 64 * PKS;   // 64 * SVS

    int tid  = threadIdx.x;
    int lane = tid & 31;
    int w    = tid >> 5;
    int g    = lane >> 2;
    int t4   = lane & 3;

    int bh = blockIdx.y;
    int b = bh / HEADS, h = bh % HEADS;
    int t0 = blockIdx.x * 128;
    size_t base  = (size_t)b * TSEQ * QKVN + (size_t)h * HD;
    size_t obase = (size_t)b * TSEQ * CDIM + (size_t)h * HD;

    const float scale = 0.03608439182435161f;   // 768^-0.5

    int krow = tid & 63;
    int kdq0 = (tid >> 6) * 4;
    int vdv  = (tid & 15) * 4;

    // ---- stage Q^T (pre-scaled) into pk ----
    #pragma unroll
    for (int it = 0; it < 8; it++) {
        int idx = tid + 256 * it;
        int r  = idx & 127;
        int dq = (idx >> 7) * 4;
        float4 qv = *(const float4*)&Q[base + (size_t)(t0 + r) * QKVN + dq];
        pk[(dq + 0) * PKS + r] = f2tf32(qv.x * scale);
        pk[(dq + 1) * PKS + r] = f2tf32(qv.y * scale);
        pk[(dq + 2) * PKS + r] = f2tf32(qv.z * scale);
        pk[(dq + 3) * PKS + r] = f2tf32(qv.w * scale);
    }

    // preload tile 0 of K/V into registers
    float4 kreg[4], vreg[4];
    #pragma unroll
    for (int it = 0; it < 4; it++) {
        kreg[it] = *(const float4*)&K[base + (size_t)krow * QKVN + kdq0 + 16 * it];
        vreg[it] = *(const float4*)&V[base + (size_t)(tid >> 4) * QKVN +
                                      (size_t)(16 * it) * QKVN + vdv];
    }

    __syncthreads();

    uint32_t qf[8][4];
    #pragma unroll
    for (int ks = 0; ks < 8; ks++) {
        int kb = ks * 8 + t4;
        int gm = 16 * w + g;
        qf[ks][0] = pk[kb * PKS + gm];
        qf[ks][1] = pk[kb * PKS + gm + 8];
        qf[ks][2] = pk[(kb + 4) * PKS + gm];
        qf[ks][3] = pk[(kb + 4) * PKS + gm + 8];
    }

    float o_acc[8][4];
    #pragma unroll
    for (int nt = 0; nt < 8; nt++)
        #pragma unroll
        for (int c = 0; c < 4; c++) o_acc[nt][c] = 0.f;
    float rm0 = -1e30f, rm1 = -1e30f, rl0 = 0.f, rl1 = 0.f;

    const int NKT = TSEQ / 64;
    for (int kt = 0; kt < NKT; kt++) {
        __syncthreads();

        #pragma unroll
        for (int it = 0; it < 4; it++) {
            int dq = kdq0 + 16 * it;
            pk[(dq + 0) * PKS + krow] = f2tf32(kreg[it].x);
            pk[(dq + 1) * PKS + krow] = f2tf32(kreg[it].y);
            pk[(dq + 2) * PKS + krow] = f2tf32(kreg[it].z);
            pk[(dq + 3) * PKS + krow] = f2tf32(kreg[it].w);
        }
        #pragma unroll
        for (int it = 0; it < 4; it++) {
            int r = (tid >> 4) + 16 * it;
            sv[r * SVS + vdv + 0] = f2tf32(vreg[it].x);
            sv[r * SVS + vdv + 1] = f2tf32(vreg[it].y);
            sv[r * SVS + vdv + 2] = f2tf32(vreg[it].z);
            sv[r * SVS + vdv + 3] = f2tf32(vreg[it].w);
        }
        __syncthreads();

        if (kt + 1 < NKT) {
            size_t snext = (size_t)(kt + 1) * 64;
            #pragma unroll
            for (int it = 0; it < 4; it++) {
                kreg[it] = *(const float4*)&K[base + (snext + krow) * QKVN +
                                              kdq0 + 16 * it];
                vreg[it] = *(const float4*)&V[base + (snext + (tid >> 4) +
                                              16 * it) * QKVN + vdv];
            }
        }

        // ---- S = Q K^T ----
        float sacc[8][4];
        #pragma unroll
        for (int nt = 0; nt < 8; nt++)
            #pragma unroll
            for (int c = 0; c < 4; c++) sacc[nt][c] = 0.f;

        #pragma unroll
        for (int ks = 0; ks < 8; ks++) {
            int kb = ks * 8 + t4;
            uint32_t bf[8][2];
            #pragma unroll
            for (int nt = 0; nt < 8; nt++) {
                int gn = nt * 8 + g;
                bf[nt][0] = pk[kb * PKS + gn];
                bf[nt][1] = pk[(kb + 4) * PKS + gn];
            }
            #pragma unroll
            for (int nt = 0; nt < 8; nt++) {
                float* d = sacc[nt];
                MMA_TF32(d, qf[ks][0], qf[ks][1], qf[ks][2], qf[ks][3],
                         bf[nt][0], bf[nt][1]);
            }
        }
        __syncthreads();

        // ---- online softmax ----
        float mx0 = -1e30f, mx1 = -1e30f;
        #pragma unroll
        for (int nt = 0; nt < 8; nt++) {
            mx0 = fmaxf(mx0, fmaxf(sacc[nt][0], sacc[nt][1]));
            mx1 = fmaxf(mx1, fmaxf(sacc[nt][2], sacc[nt][3]));
        }
        mx0 = fmaxf(mx0, __shfl_xor_sync(0xffffffffu, mx0, 1));
        mx0 = fmaxf(mx0, __shfl_xor_sync(0xffffffffu, mx0, 2));
        mx1 = fmaxf(mx1, __shfl_xor_sync(0xffffffffu, mx1, 1));
        mx1 = fmaxf(mx1, __shfl_xor_sync(0xffffffffu, mx1, 2));

        float mn0 = fmaxf(rm0, mx0);
        float mn1 = fmaxf(rm1, mx1);
        float al0 = __expf(rm0 - mn0);
        float al1 = __expf(rm1 - mn1);
        rm0 = mn0; rm1 = mn1;

        int row0 = 16 * w + g;
        int row1 = row0 + 8;
        float sum0 = 0.f, sum1 = 0.f;
        #pragma unroll
        for (int nt = 0; nt < 8; nt++) {
            int col = nt * 8 + 2 * t4;
            float p0 = __expf(sacc[nt][0] - mn0);
            float p1 = __expf(sacc[nt][1] - mn0);
            float p2 = __expf(sacc[nt][2] - mn1);
            float p3 = __expf(sacc[nt][3] - mn1);
            sum0 += p0 + p1;
            sum1 += p2 + p3;
            pk[(col + 0) * PKS + row0] = f2tf32(p0);
            pk[(col + 1) * PKS + row0] = f2tf32(p1);
            pk[(col + 0) * PKS + row1] = f2tf32(p2);
            pk[(col + 1) * PKS + row1] = f2tf32(p3);
        }
        sum0 += __shfl_xor_sync(0xffffffffu, sum0, 1);
        sum0 += __shfl_xor_sync(0xffffffffu, sum0, 2);
        sum1 += __shfl_xor_sync(0xffffffffu, sum1, 1);
        sum1 += __shfl_xor_sync(0xffffffffu, sum1, 2);
        rl0 = rl0 * al0 + sum0;
        rl1 = rl1 * al1 + sum1;

        #pragma unroll
        for (int nt = 0; nt < 8; nt++) {
            o_acc[nt][0] *= al0; o_acc[nt][1] *= al0;
            o_acc[nt][2] *= al1; o_acc[nt][3] *= al1;
        }
        __syncwarp();

        // ---- O += P V ----
        #pragma unroll
        for (int ks = 0; ks < 8; ks++) {
            int kb = ks * 8 + t4;
            int gm = 16 * w + g;
            uint32_t af0 = pk[kb * PKS + gm];
            uint32_t af1 = pk[kb * PKS + gm + 8];
            uint32_t af2 = pk[(kb + 4) * PKS + gm];
            uint32_t af3 = pk[(kb + 4) * PKS + gm + 8];
            uint32_t bf[8][2];
            #pragma unroll
            for (int nt = 0; nt < 8; nt++) {
                int gn = nt * 8 + g;
                bf[nt][0] = sv[kb * SVS + gn];
                bf[nt][1] = sv[(kb + 4) * SVS + gn];
            }
            #pragma unroll
            for (int nt = 0; nt < 8; nt++) {
                float* d = o_acc[nt];
                MMA_TF32(d, af0, af1, af2, af3, bf[nt][0], bf[nt][1]);
            }
        }
    }

    // ---- epilogue: O = acc / l ----
    float inv0 = 1.f / rl0;
    float inv1 = 1.f / rl1;
    int row0 = t0 + 16 * w + g;
    int row1 = row0 + 8;
    #pragma unroll
    for (int nt = 0; nt < 8; nt++) {
        int dcol = nt * 8 + 2 * t4;
        float2 v0, v1;
        v0.x = o_acc[nt][0] * inv0; v0.y = o_acc[nt][1] * inv0;
        v1.x = o_acc[nt][2] * inv1; v1.y = o_acc[nt][3] * inv1;
        *(float2*)&O[obase + (size_t)row0 * CDIM + dcol] = v0;
        *(float2*)&O[obase + (size_t)row1 * CDIM + dcol] = v1;
    }
}

// ---------------------------------------------------------------------------
// Launch
// ---------------------------------------------------------------------------
extern "C" void kernel_launch(void* const* d_in, const int* in_sizes, int n_in,
                              void* d_out, int out_size) {
    const float* x     = (const float*)d_in[0];
    const float* Wq    = (const float*)d_in[1];
    const float* Wk    = (const float*)d_in[2];
    const float* Wv    = (const float*)d_in[3];
    const float* Wo    = (const float*)d_in[4];
    const float* bo    = (const float*)d_in[5];
    const float* ln1_g = (const float*)d_in[6];
    const float* ln1_b = (const float*)d_in[7];
    const float* ln2_g = (const float*)d_in[8];
    const float* ln2_b = (const float*)d_in[9];
    const float* W1    = (const float*)d_in[10];
    const float* b1    = (const float*)d_in[11];
    const float* W2    = (const float*)d_in[12];
    const float* b2    = (const float*)d_in[13];
    float* out = (float*)d_out;

    float *xn, *qkv, *att, *x2, *y, *hbuf, *wqkv;
    cudaGetSymbolAddress((void**)&xn,   g_xn);
    cudaGetSymbolAddress((void**)&qkv,  g_qkv);
    cudaGetSymbolAddress((void**)&att,  g_att);
    cudaGetSymbolAddress((void**)&x2,   g_x2);
    cudaGetSymbolAddress((void**)&y,    g_y);
    cudaGetSymbolAddress((void**)&hbuf, g_h);
    cudaGetSymbolAddress((void**)&wqkv, g_wqkv);

    static bool attr_done = false;
    if (!attr_done) {
        cudaFuncSetAttribute(flash_tc_kernel,
                             cudaFuncAttributeMaxDynamicSharedMemorySize,
                             FLASH_SMEM);
        cudaFuncSetAttribute(tgemm_kernel<0,0,0>,
                             cudaFuncAttributeMaxDynamicSharedMemorySize,
                             GEMM_SMEM);
        cudaFuncSetAttribute(tgemm_kernel<0,1,1>,
                             cudaFuncAttributeMaxDynamicSharedMemorySize,
                             GEMM_SMEM);
        cudaFuncSetAttribute(tgemm_kernel<1,1,0>,
                             cudaFuncAttributeMaxDynamicSharedMemorySize,
                             GEMM_SMEM);
        attr_done = true;
    }

    // 1. repack QKV weights into fused [C, 3*H*D]
    repackqkv_kernel<<<(HEADS * CDIM * HD + 255) / 256, 256>>>(Wq, Wk, Wv, wqkv);

    // 2. LN1
    ln_kernel<<<NTOK, 256>>>(x, ln1_g, ln1_b, xn);

    // 3. fused QKV projection: [8192,768] x [768,2304]
    {
        dim3 grid(QKVN / 128, NTOK / 128);
        tgemm_kernel<0,0,0><<<grid, 256, GEMM_SMEM>>>(xn, wqkv, nullptr, nullptr,
                                                      qkv, NTOK, QKVN, CDIM);
    }

    // 4. tensor-core flash attention (Q/K/V strided views into qkv)
    {
        dim3 grid(TSEQ / 128, BB * HEADS);
        flash_tc_kernel<<<grid, 256, FLASH_SMEM>>>(qkv, qkv + CDIM,
                                                   qkv + 2 * CDIM, att);
    }

    // 5. output projection + bias + residual(x) -> x2
    {
        dim3 grid(CDIM / 128, NTOK / 128);
        tgemm_kernel<0,1,1><<<grid, 256, GEMM_SMEM>>>(att, Wo, bo, x, x2,
                                                      NTOK, CDIM, CDIM);
    }

    // 6. LN2
    ln_kernel<<<NTOK, 256>>>(x2, ln2_g, ln2_b, y);

    // 7. FC1 + bias + GELU
    {
        dim3 grid(MLPD / 128, NTOK / 128);
        tgemm_kernel<1,1,0><<<grid, 256, GEMM_SMEM>>>(y, W1, b1, nullptr, hbuf,
                                                      NTOK, MLPD, CDIM);
    }

    // 8. FC2 + bias + residual(x2) -> out
    {
        dim3 grid(CDIM / 128, NTOK / 128);
        tgemm_kernel<0,1,1><<<grid, 256, GEMM_SMEM>>>(hbuf, W2, b2, x2, out,
                                                      NTOK, CDIM, MLPD);
    }
}

// round 11
// speedup vs baseline: 1.0014x; 1.0014x over previous
#include <cuda_runtime.h>
#include <math.h>
#include <stdint.h>

// Problem constants
#define BB    4
#define TSEQ  2048
#define CDIM  768
#define HEADS 12
#define HD    64
#define MLPD  3072
#define NTOK  (BB*TSEQ)          // 8192
#define QKVN  (3*CDIM)           // 2304

// ---------------------------------------------------------------------------
// Scratch (device globals; no allocation allowed)
// ---------------------------------------------------------------------------
__device__ float g_xn  [NTOK*CDIM];
__device__ float g_qkv [NTOK*QKVN];
__device__ float g_att [NTOK*CDIM];
__device__ float g_x2  [NTOK*CDIM];
__device__ float g_y   [NTOK*CDIM];
__device__ float g_h   [NTOK*MLPD];
__device__ float g_wqkv[CDIM*QKVN];

// ---------------------------------------------------------------------------
// Repack [H,C,D] x3 -> fused [C, 3*H*D]
// ---------------------------------------------------------------------------
__global__ void repackqkv_kernel(const float* __restrict__ wq,
                                 const float* __restrict__ wk,
                                 const float* __restrict__ wv,
                                 float* __restrict__ o) {
    int i = blockIdx.x * 256 + threadIdx.x;
    if (i >= HEADS * CDIM * HD) return;
    int h = i / (CDIM * HD);
    int r = i % (CDIM * HD);
    int c = r / HD;
    int d = r % HD;
    size_t base = (size_t)c * QKVN + h * HD + d;
    o[base]            = wq[i];
    o[base + CDIM]     = wk[i];
    o[base + 2*CDIM]   = wv[i];
}

// ---------------------------------------------------------------------------
// LayerNorm: one block per token row, 256 threads, C=768 -> 3 elems/thread
// ---------------------------------------------------------------------------
__global__ void ln_kernel(const float* __restrict__ x,
                          const float* __restrict__ g,
                          const float* __restrict__ b,
                          float* __restrict__ out) {
    int row = blockIdx.x;
    int tid = threadIdx.x;
    const float* xr = x + (size_t)row * CDIM;

    float v0 = xr[tid];
    float v1 = xr[tid + 256];
    float v2 = xr[tid + 512];
    float s  = v0 + v1 + v2;
    float s2 = v0*v0 + v1*v1 + v2*v2;

    #pragma unroll
    for (int o = 16; o > 0; o >>= 1) {
        s  += __shfl_xor_sync(0xffffffffu, s,  o);
        s2 += __shfl_xor_sync(0xffffffffu, s2, o);
    }
    __shared__ float rs[8], rs2[8];
    int w = tid >> 5, l = tid & 31;
    if (l == 0) { rs[w] = s; rs2[w] = s2; }
    __syncthreads();
    if (tid < 32) {
        float a  = (l < 8) ? rs[l]  : 0.f;
        float a2 = (l < 8) ? rs2[l] : 0.f;
        #pragma unroll
        for (int o = 4; o > 0; o >>= 1) {
            a  += __shfl_xor_sync(0xffffffffu, a,  o);
            a2 += __shfl_xor_sync(0xffffffffu, a2, o);
        }
        if (l == 0) { rs[0] = a; rs2[0] = a2; }
    }
    __syncthreads();
    float mu  = rs[0] * (1.f / CDIM);
    float var = rs2[0] * (1.f / CDIM) - mu * mu;
    float inv = rsqrtf(var + 1e-6f);

    float* orow = out + (size_t)row * CDIM;
    orow[tid]       = (v0 - mu) * inv * g[tid]       + b[tid];
    orow[tid + 256] = (v1 - mu) * inv * g[tid + 256] + b[tid + 256];
    orow[tid + 512] = (v2 - mu) * inv * g[tid + 512] + b[tid + 512];
}

// ---------------------------------------------------------------------------
// Common helpers
// ---------------------------------------------------------------------------
__device__ __forceinline__ float gelu_exact(float v) {
    return 0.5f * v * (1.0f + erff(v * 0.70710678118654752f));
}

__device__ __forceinline__ uint32_t f2tf32(float f) {
    uint32_t u;
    asm("cvt.rna.tf32.f32 %0, %1;" : "=r"(u) : "f"(f));
    return u;
}

#define MMA_TF32(d, a0,a1,a2,a3, b0,b1)                                      \
    asm volatile(                                                            \
        "mma.sync.aligned.m16n8k8.row.col.f32.tf32.tf32.f32 "                \
        "{%0,%1,%2,%3}, {%4,%5,%6,%7}, {%8,%9}, {%0,%1,%2,%3};"              \
        : "+f"(d[0]), "+f"(d[1]), "+f"(d[2]), "+f"(d[3])                     \
        : "r"(a0), "r"(a1), "r"(a2), "r"(a3), "r"(b0), "r"(b1))

__device__ __forceinline__ void cp16(float* dst_smem, const float* src_gmem) {
    uint32_t d = (uint32_t)__cvta_generic_to_shared(dst_smem);
    asm volatile("cp.async.cg.shared.global [%0], [%1], 16;\n"
                 :: "r"(d), "l"(src_gmem));
}
#define CP_COMMIT()  asm volatile("cp.async.commit_group;\n" ::: "memory")
#define CP_WAIT(n)   asm volatile("cp.async.wait_group %0;\n" :: "n"(n) : "memory")

// ---------------------------------------------------------------------------
// TF32 tensor-core GEMM v2: 3-stage cp.async pipeline.
// C = act(A[M,K] @ B[K,N] + bias) + res
// 128x128 tile, BK=32, 256 threads (8 warps 2x4), mma.m16n8k8.tf32.
// smem per stage: sA [128 m][36]  (stride 36 -> frag bank 4*gq+t4, bijective)
//                 sB [32 k][136]  (stride 136 -> frag bank 8*t4+gq, bijective)
// cp.async stores hit the conflict-free 4-phase floor on both tiles.
// mma consumes raw f32 bits (HW tf32 truncation) — no cvt in the hot loop.
// ---------------------------------------------------------------------------
#define AST 36
#define BST 136
#define STG_WORDS (128*AST + 32*BST)      // 8960 words = 35840 B
#define NSTAGE 3
#define GEMM_SMEM (NSTAGE*STG_WORDS*4)    // 107520 B

template<int ACT, int HASBIAS, int HASRES>
__global__ void __launch_bounds__(256, 2)
tgemm_kernel(const float* __restrict__ A, const float* __restrict__ B,
             const float* __restrict__ bias, const float* __restrict__ res,
             float* __restrict__ C, int M, int N, int K) {
    extern __shared__ float smg[];

    int tid  = threadIdx.x;
    int lane = tid & 31;
    int warp = tid >> 5;
    int wm = warp >> 2;            // 0..1 -> 64 rows each
    int wn = warp & 3;             // 0..3 -> 32 cols each
    int t4 = lane & 3;
    int gq = lane >> 2;
    int m0 = blockIdx.y * 128, n0 = blockIdx.x * 128;

    // A loader: thread covers row arow, k-half ap (4 x 16B chunks)
    int arow = tid >> 1;
    int ap   = tid & 1;
    const float* Ap = A + (size_t)(m0 + arow) * K + ap * 16;
    // B loader: thread covers k-row brow, col chunks bch + 32c
    int brow = tid >> 3;
    int bch  = (tid & 7) * 4;
    const float* Bp = B + (size_t)brow * N + n0 + bch;

    float acc[4][4][4];
    #pragma unroll
    for (int a = 0; a < 4; a++)
        #pragma unroll
        for (int b = 0; b < 4; b++)
            #pragma unroll
            for (int c = 0; c < 4; c++) acc[a][b][c] = 0.f;

    const int NK = K / 32;

    // prologue: issue stages 0..NSTAGE-2
    #pragma unroll
    for (int s = 0; s < NSTAGE - 1; s++) {
        float* sa = smg + s * STG_WORDS;
        float* sb = sa + 128 * AST;
        int k0 = s * 32;
        #pragma unroll
        for (int c = 0; c < 4; c++)
            cp16(&sa[arow * AST + ap * 16 + c * 4], Ap + k0 + c * 4);
        #pragma unroll
        for (int c = 0; c < 4; c++)
            cp16(&sb[brow * BST + bch + c * 32],
                 Bp + (size_t)k0 * N + c * 32);
        CP_COMMIT();
    }

    for (int i = 0; i < NK; i++) {
        CP_WAIT(NSTAGE - 2);
        __syncthreads();

        const uint32_t* sa = (const uint32_t*)(smg + (i % NSTAGE) * STG_WORDS);
        const uint32_t* sb = sa + 128 * AST;

        #pragma unroll
        for (int ks = 0; ks < 4; ks++) {
            int kb = ks * 8 + t4;
            uint32_t bf[4][2];
            #pragma unroll
            for (int nt = 0; nt < 4; nt++) {
                int gn = wn * 32 + nt * 8 + gq;
                bf[nt][0] = sb[kb * BST + gn];
                bf[nt][1] = sb[(kb + 4) * BST + gn];
            }
            uint32_t af[4][4];
            #pragma unroll
            for (int mt = 0; mt < 4; mt++) {
                int gm = wm * 64 + mt * 16 + gq;
                af[mt][0] = sa[gm * AST + kb];           // A[g][t4]
                af[mt][1] = sa[(gm + 8) * AST + kb];     // A[g+8][t4]
                af[mt][2] = sa[gm * AST + kb + 4];       // A[g][t4+4]
                af[mt][3] = sa[(gm + 8) * AST + kb + 4]; // A[g+8][t4+4]
            }
            #pragma unroll
            for (int mt = 0; mt < 4; mt++)
                #pragma unroll
                for (int nt = 0; nt < 4; nt++) {
                    float* d = acc[mt][nt];
                    MMA_TF32(d, af[mt][0], af[mt][1], af[mt][2], af[mt][3],
                             bf[nt][0], bf[nt][1]);
                }
        }

        // issue tile i+NSTAGE-1 (or empty group to keep wait counts valid)
        int nt_ = i + NSTAGE - 1;
        if (nt_ < NK) {
            float* sa_w = smg + (nt_ % NSTAGE) * STG_WORDS;
            float* sb_w = sa_w + 128 * AST;
            int k0 = nt_ * 32;
            #pragma unroll
            for (int c = 0; c < 4; c++)
                cp16(&sa_w[arow * AST + ap * 16 + c * 4], Ap + k0 + c * 4);
            #pragma unroll
            for (int c = 0; c < 4; c++)
                cp16(&sb_w[brow * BST + bch + c * 32],
                     Bp + (size_t)k0 * N + c * 32);
        }
        CP_COMMIT();
    }

    // Epilogue
    #pragma unroll
    for (int mt = 0; mt < 4; mt++) {
        int gr = m0 + wm * 64 + mt * 16 + gq;
        #pragma unroll
        for (int nt = 0; nt < 4; nt++) {
            int gc = n0 + wn * 32 + nt * 8 + t4 * 2;
            float2 v0, v1;
            v0.x = acc[mt][nt][0]; v0.y = acc[mt][nt][1];
            v1.x = acc[mt][nt][2]; v1.y = acc[mt][nt][3];
            if (HASBIAS) {
                float2 bb = *(const float2*)&bias[gc];
                v0.x += bb.x; v0.y += bb.y;
                v1.x += bb.x; v1.y += bb.y;
            }
            if (ACT == 1) {
                v0.x = gelu_exact(v0.x); v0.y = gelu_exact(v0.y);
                v1.x = gelu_exact(v1.x); v1.y = gelu_exact(v1.y);
            }
            if (HASRES) {
                float2 r0 = *(const float2*)&res[(size_t)gr * N + gc];
                float2 r1 = *(const float2*)&res[(size_t)(gr + 8) * N + gc];
                v0.x += r0.x; v0.y += r0.y;
                v1.x += r1.x; v1.y += r1.y;
            }
            *(float2*)&C[(size_t)gr * N + gc]       = v0;
            *(float2*)&C[(size_t)(gr + 8) * N + gc] = v1;
        }
    }
}

// ---------------------------------------------------------------------------
// Tensor-core flash attention v3: register-prefetched K/V tiles.
// Per (b,h): BR=128 query rows / block (8 warps x 16 rows), BC=64 kv tile.
// Dynamic smem (53.2KB): pk[64][136] (Q^T / K^T / P), sv[64][72] (V).
// ---------------------------------------------------------------------------
#define PKS 136
#define SVS 72
#define FLASH_SMEM ((64*PKS + 64*SVS) * 4)

__global__ void __launch_bounds__(256, 1)
flash_tc_kernel(const float* __restrict__ Q, const float* __restrict__ K,
                const float* __restrict__ V, float* __restrict__ O) {
    extern __shared__ uint32_t smf[];
    uint32_t* pk = smf;              // 64 * PKS
    uint32_t* sv = smf + 64 * PKS;   // 64 * SVS

    int tid  = threadIdx.x;
    int lane = tid & 31;
    int w    = tid >> 5;
    int g    = lane >> 2;
    int t4   = lane & 3;

    int bh = blockIdx.y;
    int b = bh / HEADS, h = bh % HEADS;
    int t0 = blockIdx.x * 128;
    size_t base  = (size_t)b * TSEQ * QKVN + (size_t)h * HD;
    size_t obase = (size_t)b * TSEQ * CDIM + (size_t)h * HD;

    const float scale = 0.03608439182435161f;   // 768^-0.5

    int krow = tid & 63;
    int kdq0 = (tid >> 6) * 4;
    int vdv  = (tid & 15) * 4;

    // ---- stage Q^T (pre-scaled) into pk ----
    #pragma unroll
    for (int it = 0; it < 8; it++) {
        int idx = tid + 256 * it;
        int r  = idx & 127;
        int dq = (idx >> 7) * 4;
        float4 qv = *(const float4*)&Q[base + (size_t)(t0 + r) * QKVN + dq];
        pk[(dq + 0) * PKS + r] = f2tf32(qv.x * scale);
        pk[(dq + 1) * PKS + r] = f2tf32(qv.y * scale);
        pk[(dq + 2) * PKS + r] = f2tf32(qv.z * scale);
        pk[(dq + 3) * PKS + r] = f2tf32(qv.w * scale);
    }

    // preload tile 0 of K/V into registers
    float4 kreg[4], vreg[4];
    #pragma unroll
    for (int it = 0; it < 4; it++) {
        kreg[it] = *(const float4*)&K[base + (size_t)krow * QKVN + kdq0 + 16 * it];
        vreg[it] = *(const float4*)&V[base + (size_t)(tid >> 4) * QKVN +
                                      (size_t)(16 * it) * QKVN + vdv];
    }

    __syncthreads();

    uint32_t qf[8][4];
    #pragma unroll
    for (int ks = 0; ks < 8; ks++) {
        int kb = ks * 8 + t4;
        int gm = 16 * w + g;
        qf[ks][0] = pk[kb * PKS + gm];
        qf[ks][1] = pk[kb * PKS + gm + 8];
        qf[ks][2] = pk[(kb + 4) * PKS + gm];
        qf[ks][3] = pk[(kb + 4) * PKS + gm + 8];
    }

    float o_acc[8][4];
    #pragma unroll
    for (int nt = 0; nt < 8; nt++)
        #pragma unroll
        for (int c = 0; c < 4; c++) o_acc[nt][c] = 0.f;
    float rm0 = -1e30f, rm1 = -1e30f, rl0 = 0.f, rl1 = 0.f;

    const int NKT = TSEQ / 64;
    for (int kt = 0; kt < NKT; kt++) {
        __syncthreads();

        #pragma unroll
        for (int it = 0; it < 4; it++) {
            int dq = kdq0 + 16 * it;
            pk[(dq + 0) * PKS + krow] = f2tf32(kreg[it].x);
            pk[(dq + 1) * PKS + krow] = f2tf32(kreg[it].y);
            pk[(dq + 2) * PKS + krow] = f2tf32(kreg[it].z);
            pk[(dq + 3) * PKS + krow] = f2tf32(kreg[it].w);
        }
        #pragma unroll
        for (int it = 0; it < 4; it++) {
            int r = (tid >> 4) + 16 * it;
            sv[r * SVS + vdv + 0] = f2tf32(vreg[it].x);
            sv[r * SVS + vdv + 1] = f2tf32(vreg[it].y);
            sv[r * SVS + vdv + 2] = f2tf32(vreg[it].z);
            sv[r * SVS + vdv + 3] = f2tf32(vreg[it].w);
        }
        __syncthreads();

        if (kt + 1 < NKT) {
            size_t snext = (size_t)(kt + 1) * 64;
            #pragma unroll
            for (int it = 0; it < 4; it++) {
                kreg[it] = *(const float4*)&K[base + (snext + krow) * QKVN +
                                              kdq0 + 16 * it];
                vreg[it] = *(const float4*)&V[base + (snext + (tid >> 4) +
                                              16 * it) * QKVN + vdv];
            }
        }

        // ---- S = Q K^T ----
        float sacc[8][4];
        #pragma unroll
        for (int nt = 0; nt < 8; nt++)
            #pragma unroll
            for (int c = 0; c < 4; c++) sacc[nt][c] = 0.f;

        #pragma unroll
        for (int ks = 0; ks < 8; ks++) {
            int kb = ks * 8 + t4;
            uint32_t bf[8][2];
            #pragma unroll
            for (int nt = 0; nt < 8; nt++) {
                int gn = nt * 8 + g;
                bf[nt][0] = pk[kb * PKS + gn];
                bf[nt][1] = pk[(kb + 4) * PKS + gn];
            }
            #pragma unroll
            for (int nt = 0; nt < 8; nt++) {
                float* d = sacc[nt];
                MMA_TF32(d, qf[ks][0], qf[ks][1], qf[ks][2], qf[ks][3],
                         bf[nt][0], bf[nt][1]);
            }
        }
        __syncthreads();

        // ---- online softmax ----
        float mx0 = -1e30f, mx1 = -1e30f;
        #pragma unroll
        for (int nt = 0; nt < 8; nt++) {
            mx0 = fmaxf(mx0, fmaxf(sacc[nt][0], sacc[nt][1]));
            mx1 = fmaxf(mx1, fmaxf(sacc[nt][2], sacc[nt][3]));
        }
        mx0 = fmaxf(mx0, __shfl_xor_sync(0xffffffffu, mx0, 1));
        mx0 = fmaxf(mx0, __shfl_xor_sync(0xffffffffu, mx0, 2));
        mx1 = fmaxf(mx1, __shfl_xor_sync(0xffffffffu, mx1, 1));
        mx1 = fmaxf(mx1, __shfl_xor_sync(0xffffffffu, mx1, 2));

        float mn0 = fmaxf(rm0, mx0);
        float mn1 = fmaxf(rm1, mx1);
        float al0 = __expf(rm0 - mn0);
        float al1 = __expf(rm1 - mn1);
        rm0 = mn0; rm1 = mn1;

        int row0 = 16 * w + g;
        int row1 = row0 + 8;
        float sum0 = 0.f, sum1 = 0.f;
        #pragma unroll
        for (int nt = 0; nt < 8; nt++) {
            int col = nt * 8 + 2 * t4;
            float p0 = __expf(sacc[nt][0] - mn0);
            float p1 = __expf(sacc[nt][1] - mn0);
            float p2 = __expf(sacc[nt][2] - mn1);
            float p3 = __expf(sacc[nt][3] - mn1);
            sum0 += p0 + p1;
            sum1 += p2 + p3;
            pk[(col + 0) * PKS + row0] = f2tf32(p0);
            pk[(col + 1) * PKS + row0] = f2tf32(p1);
            pk[(col + 0) * PKS + row1] = f2tf32(p2);
            pk[(col + 1) * PKS + row1] = f2tf32(p3);
        }
        sum0 += __shfl_xor_sync(0xffffffffu, sum0, 1);
        sum0 += __shfl_xor_sync(0xffffffffu, sum0, 2);
        sum1 += __shfl_xor_sync(0xffffffffu, sum1, 1);
        sum1 += __shfl_xor_sync(0xffffffffu, sum1, 2);
        rl0 = rl0 * al0 + sum0;
        rl1 = rl1 * al1 + sum1;

        #pragma unroll
        for (int nt = 0; nt < 8; nt++) {
            o_acc[nt][0] *= al0; o_acc[nt][1] *= al0;
            o_acc[nt][2] *= al1; o_acc[nt][3] *= al1;
        }
        __syncwarp();

        // ---- O += P V ----
        #pragma unroll
        for (int ks = 0; ks < 8; ks++) {
            int kb = ks * 8 + t4;
            int gm = 16 * w + g;
            uint32_t af0 = pk[kb * PKS + gm];
            uint32_t af1 = pk[kb * PKS + gm + 8];
            uint32_t af2 = pk[(kb + 4) * PKS + gm];
            uint32_t af3 = pk[(kb + 4) * PKS + gm + 8];
            uint32_t bf[8][2];
            #pragma unroll
            for (int nt = 0; nt < 8; nt++) {
                int gn = nt * 8 + g;
                bf[nt][0] = sv[kb * SVS + gn];
                bf[nt][1] = sv[(kb + 4) * SVS + gn];
            }
            #pragma unroll
            for (int nt = 0; nt < 8; nt++) {
                float* d = o_acc[nt];
                MMA_TF32(d, af0, af1, af2, af3, bf[nt][0], bf[nt][1]);
            }
        }
    }

    // ---- epilogue: O = acc / l ----
    float inv0 = 1.f / rl0;
    float inv1 = 1.f / rl1;
    int row0 = t0 + 16 * w + g;
    int row1 = row0 + 8;
    #pragma unroll
    for (int nt = 0; nt < 8; nt++) {
        int dcol = nt * 8 + 2 * t4;
        float2 v0, v1;
        v0.x = o_acc[nt][0] * inv0; v0.y = o_acc[nt][1] * inv0;
        v1.x = o_acc[nt][2] * inv1; v1.y = o_acc[nt][3] * inv1;
        *(float2*)&O[obase + (size_t)row0 * CDIM + dcol] = v0;
        *(float2*)&O[obase + (size_t)row1 * CDIM + dcol] = v1;
    }
}

// ---------------------------------------------------------------------------
// Launch
// ---------------------------------------------------------------------------
extern "C" void kernel_launch(void* const* d_in, const int* in_sizes, int n_in,
                              void* d_out, int out_size) {
    const float* x     = (const float*)d_in[0];
    const float* Wq    = (const float*)d_in[1];
    const float* Wk    = (const float*)d_in[2];
    const float* Wv    = (const float*)d_in[3];
    const float* Wo    = (const float*)d_in[4];
    const float* bo    = (const float*)d_in[5];
    const float* ln1_g = (const float*)d_in[6];
    const float* ln1_b = (const float*)d_in[7];
    const float* ln2_g = (const float*)d_in[8];
    const float* ln2_b = (const float*)d_in[9];
    const float* W1    = (const float*)d_in[10];
    const float* b1    = (const float*)d_in[11];
    const float* W2    = (const float*)d_in[12];
    const float* b2    = (const float*)d_in[13];
    float* out = (float*)d_out;

    float *xn, *qkv, *att, *x2, *y, *hbuf, *wqkv;
    cudaGetSymbolAddress((void**)&xn,   g_xn);
    cudaGetSymbolAddress((void**)&qkv,  g_qkv);
    cudaGetSymbolAddress((void**)&att,  g_att);
    cudaGetSymbolAddress((void**)&x2,   g_x2);
    cudaGetSymbolAddress((void**)&y,    g_y);
    cudaGetSymbolAddress((void**)&hbuf, g_h);
    cudaGetSymbolAddress((void**)&wqkv, g_wqkv);

    static bool attr_done = false;
    if (!attr_done) {
        cudaFuncSetAttribute(flash_tc_kernel,
                             cudaFuncAttributeMaxDynamicSharedMemorySize,
                             FLASH_SMEM);
        cudaFuncSetAttribute(tgemm_kernel<0,0,0>,
                             cudaFuncAttributeMaxDynamicSharedMemorySize,
                             GEMM_SMEM);
        cudaFuncSetAttribute(tgemm_kernel<0,1,1>,
                             cudaFuncAttributeMaxDynamicSharedMemorySize,
                             GEMM_SMEM);
        cudaFuncSetAttribute(tgemm_kernel<1,1,0>,
                             cudaFuncAttributeMaxDynamicSharedMemorySize,
                             GEMM_SMEM);
        attr_done = true;
    }

    // 1. repack QKV weights into fused [C, 3*H*D]
    repackqkv_kernel<<<(HEADS * CDIM * HD + 255) / 256, 256>>>(Wq, Wk, Wv, wqkv);

    // 2. LN1
    ln_kernel<<<NTOK, 256>>>(x, ln1_g, ln1_b, xn);

    // 3. fused QKV projection: [8192,768] x [768,2304]
    {
        dim3 grid(QKVN / 128, NTOK / 128);
        tgemm_kernel<0,0,0><<<grid, 256, GEMM_SMEM>>>(xn, wqkv, nullptr, nullptr,
                                                      qkv, NTOK, QKVN, CDIM);
    }

    // 4. tensor-core flash attention (Q/K/V strided views into qkv)
    {
        dim3 grid(TSEQ / 128, BB * HEADS);
        flash_tc_kernel<<<grid, 256, FLASH_SMEM>>>(qkv, qkv + CDIM,
                                                   qkv + 2 * CDIM, att);
    }

    // 5. output projection + bias + residual(x) -> x2
    {
        dim3 grid(CDIM / 128, NTOK / 128);
        tgemm_kernel<0,1,1><<<grid, 256, GEMM_SMEM>>>(att, Wo, bo, x, x2,
                                                      NTOK, CDIM, CDIM);
    }

    // 6. LN2
    ln_kernel<<<NTOK, 256>>>(x2, ln2_g, ln2_b, y);

    // 7. FC1 + bias + GELU
    {
        dim3 grid(MLPD / 128, NTOK / 128);
        tgemm_kernel<1,1,0><<<grid, 256, GEMM_SMEM>>>(y, W1, b1, nullptr, hbuf,
                                                      NTOK, MLPD, CDIM);
    }

    // 8. FC2 + bias + residual(x2) -> out
    {
        dim3 grid(CDIM / 128, NTOK / 128);
        tgemm_kernel<0,1,1><<<grid, 256, GEMM_SMEM>>>(hbuf, W2, b2, x2, out,
                                                      NTOK, CDIM, MLPD);
    }
}

// round 14
// speedup vs baseline: 1.0898x; 1.0882x over previous
#include <cuda_runtime.h>
#include <math.h>
#include <stdint.h>

// Problem constants
#define BB    4
#define TSEQ  2048
#define CDIM  768
#define HEADS 12
#define HD    64
#define MLPD  3072
#define NTOK  (BB*TSEQ)          // 8192
#define QKVN  (3*CDIM)           // 2304

// ---------------------------------------------------------------------------
// Scratch (device globals; no allocation allowed)
// ---------------------------------------------------------------------------
__device__ float g_xn  [NTOK*CDIM];
__device__ float g_qkv [NTOK*QKVN];
__device__ float g_att [NTOK*CDIM];
__device__ float g_x2  [NTOK*CDIM];
__device__ float g_y   [NTOK*CDIM];
__device__ float g_h   [NTOK*MLPD];
__device__ float g_wqkv[CDIM*QKVN];

// ---------------------------------------------------------------------------
// Repack [H,C,D] x3 -> fused [C, 3*H*D]
// ---------------------------------------------------------------------------
__global__ void repackqkv_kernel(const float* __restrict__ wq,
                                 const float* __restrict__ wk,
                                 const float* __restrict__ wv,
                                 float* __restrict__ o) {
    int i = blockIdx.x * 256 + threadIdx.x;
    if (i >= HEADS * CDIM * HD) return;
    int h = i / (CDIM * HD);
    int r = i % (CDIM * HD);
    int c = r / HD;
    int d = r % HD;
    size_t base = (size_t)c * QKVN + h * HD + d;
    o[base]            = wq[i];
    o[base + CDIM]     = wk[i];
    o[base + 2*CDIM]   = wv[i];
}

// ---------------------------------------------------------------------------
// LayerNorm: one block per token row, 256 threads, C=768 -> 3 elems/thread
// ---------------------------------------------------------------------------
__global__ void ln_kernel(const float* __restrict__ x,
                          const float* __restrict__ g,
                          const float* __restrict__ b,
                          float* __restrict__ out) {
    int row = blockIdx.x;
    int tid = threadIdx.x;
    const float* xr = x + (size_t)row * CDIM;

    float v0 = xr[tid];
    float v1 = xr[tid + 256];
    float v2 = xr[tid + 512];
    float s  = v0 + v1 + v2;
    float s2 = v0*v0 + v1*v1 + v2*v2;

    #pragma unroll
    for (int o = 16; o > 0; o >>= 1) {
        s  += __shfl_xor_sync(0xffffffffu, s,  o);
        s2 += __shfl_xor_sync(0xffffffffu, s2, o);
    }
    __shared__ float rs[8], rs2[8];
    int w = tid >> 5, l = tid & 31;
    if (l == 0) { rs[w] = s; rs2[w] = s2; }
    __syncthreads();
    if (tid < 32) {
        float a  = (l < 8) ? rs[l]  : 0.f;
        float a2 = (l < 8) ? rs2[l] : 0.f;
        #pragma unroll
        for (int o = 4; o > 0; o >>= 1) {
            a  += __shfl_xor_sync(0xffffffffu, a,  o);
            a2 += __shfl_xor_sync(0xffffffffu, a2, o);
        }
        if (l == 0) { rs[0] = a; rs2[0] = a2; }
    }
    __syncthreads();
    float mu  = rs[0] * (1.f / CDIM);
    float var = rs2[0] * (1.f / CDIM) - mu * mu;
    float inv = rsqrtf(var + 1e-6f);

    float* orow = out + (size_t)row * CDIM;
    orow[tid]       = (v0 - mu) * inv * g[tid]       + b[tid];
    orow[tid + 256] = (v1 - mu) * inv * g[tid + 256] + b[tid + 256];
    orow[tid + 512] = (v2 - mu) * inv * g[tid + 512] + b[tid + 512];
}

// ---------------------------------------------------------------------------
// Common helpers
// ---------------------------------------------------------------------------
__device__ __forceinline__ float gelu_exact(float v) {
    return 0.5f * v * (1.0f + erff(v * 0.70710678118654752f));
}

__device__ __forceinline__ uint32_t f2tf32(float f) {
    uint32_t u;
    asm("cvt.rna.tf32.f32 %0, %1;" : "=r"(u) : "f"(f));
    return u;
}

#define MMA_TF32(d, a0,a1,a2,a3, b0,b1)                                      \
    asm volatile(                                                            \
        "mma.sync.aligned.m16n8k8.row.col.f32.tf32.tf32.f32 "                \
        "{%0,%1,%2,%3}, {%4,%5,%6,%7}, {%8,%9}, {%0,%1,%2,%3};"              \
        : "+f"(d[0]), "+f"(d[1]), "+f"(d[2]), "+f"(d[3])                     \
        : "r"(a0), "r"(a1), "r"(a2), "r"(a3), "r"(b0), "r"(b1))

__device__ __forceinline__ void cp16(float* dst_smem, const float* src_gmem) {
    uint32_t d = (uint32_t)__cvta_generic_to_shared(dst_smem);
    asm volatile("cp.async.cg.shared.global [%0], [%1], 16;\n"
                 :: "r"(d), "l"(src_gmem));
}
#define CP_COMMIT()  asm volatile("cp.async.commit_group;\n" ::: "memory")
#define CP_WAIT(n)   asm volatile("cp.async.wait_group %0;\n" :: "n"(n) : "memory")

// ---------------------------------------------------------------------------
// TF32 tensor-core GEMM v2: 3-stage cp.async pipeline (unchanged from R8).
// ---------------------------------------------------------------------------
#define AST 36
#define BST 136
#define STG_WORDS (128*AST + 32*BST)      // 8960 words = 35840 B
#define NSTAGE 3
#define GEMM_SMEM (NSTAGE*STG_WORDS*4)    // 107520 B

template<int ACT, int HASBIAS, int HASRES>
__global__ void __launch_bounds__(256, 2)
tgemm_kernel(const float* __restrict__ A, const float* __restrict__ B,
             const float* __restrict__ bias, const float* __restrict__ res,
             float* __restrict__ C, int M, int N, int K) {
    extern __shared__ float smg[];

    int tid  = threadIdx.x;
    int lane = tid & 31;
    int warp = tid >> 5;
    int wm = warp >> 2;
    int wn = warp & 3;
    int t4 = lane & 3;
    int gq = lane >> 2;
    int m0 = blockIdx.y * 128, n0 = blockIdx.x * 128;

    int arow = tid >> 1;
    int ap   = tid & 1;
    const float* Ap = A + (size_t)(m0 + arow) * K + ap * 16;
    int brow = tid >> 3;
    int bch  = (tid & 7) * 4;
    const float* Bp = B + (size_t)brow * N + n0 + bch;

    float acc[4][4][4];
    #pragma unroll
    for (int a = 0; a < 4; a++)
        #pragma unroll
        for (int b = 0; b < 4; b++)
            #pragma unroll
            for (int c = 0; c < 4; c++) acc[a][b][c] = 0.f;

    const int NK = K / 32;

    #pragma unroll
    for (int s = 0; s < NSTAGE - 1; s++) {
        float* sa = smg + s * STG_WORDS;
        float* sb = sa + 128 * AST;
        int k0 = s * 32;
        #pragma unroll
        for (int c = 0; c < 4; c++)
            cp16(&sa[arow * AST + ap * 16 + c * 4], Ap + k0 + c * 4);
        #pragma unroll
        for (int c = 0; c < 4; c++)
            cp16(&sb[brow * BST + bch + c * 32],
                 Bp + (size_t)k0 * N + c * 32);
        CP_COMMIT();
    }

    for (int i = 0; i < NK; i++) {
        CP_WAIT(NSTAGE - 2);
        __syncthreads();

        const uint32_t* sa = (const uint32_t*)(smg + (i % NSTAGE) * STG_WORDS);
        const uint32_t* sb = sa + 128 * AST;

        #pragma unroll
        for (int ks = 0; ks < 4; ks++) {
            int kb = ks * 8 + t4;
            uint32_t bf[4][2];
            #pragma unroll
            for (int nt = 0; nt < 4; nt++) {
                int gn = wn * 32 + nt * 8 + gq;
                bf[nt][0] = sb[kb * BST + gn];
                bf[nt][1] = sb[(kb + 4) * BST + gn];
            }
            uint32_t af[4][4];
            #pragma unroll
            for (int mt = 0; mt < 4; mt++) {
                int gm = wm * 64 + mt * 16 + gq;
                af[mt][0] = sa[gm * AST + kb];
                af[mt][1] = sa[(gm + 8) * AST + kb];
                af[mt][2] = sa[gm * AST + kb + 4];
                af[mt][3] = sa[(gm + 8) * AST + kb + 4];
            }
            #pragma unroll
            for (int mt = 0; mt < 4; mt++)
                #pragma unroll
                for (int nt = 0; nt < 4; nt++) {
                    float* d = acc[mt][nt];
                    MMA_TF32(d, af[mt][0], af[mt][1], af[mt][2], af[mt][3],
                             bf[nt][0], bf[nt][1]);
                }
        }

        int nt_ = i + NSTAGE - 1;
        if (nt_ < NK) {
            float* sa_w = smg + (nt_ % NSTAGE) * STG_WORDS;
            float* sb_w = sa_w + 128 * AST;
            int k0 = nt_ * 32;
            #pragma unroll
            for (int c = 0; c < 4; c++)
                cp16(&sa_w[arow * AST + ap * 16 + c * 4], Ap + k0 + c * 4);
            #pragma unroll
            for (int c = 0; c < 4; c++)
                cp16(&sb_w[brow * BST + bch + c * 32],
                     Bp + (size_t)k0 * N + c * 32);
        }
        CP_COMMIT();
    }

    #pragma unroll
    for (int mt = 0; mt < 4; mt++) {
        int gr = m0 + wm * 64 + mt * 16 + gq;
        #pragma unroll
        for (int nt = 0; nt < 4; nt++) {
            int gc = n0 + wn * 32 + nt * 8 + t4 * 2;
            float2 v0, v1;
            v0.x = acc[mt][nt][0]; v0.y = acc[mt][nt][1];
            v1.x = acc[mt][nt][2]; v1.y = acc[mt][nt][3];
            if (HASBIAS) {
                float2 bb = *(const float2*)&bias[gc];
                v0.x += bb.x; v0.y += bb.y;
                v1.x += bb.x; v1.y += bb.y;
            }
            if (ACT == 1) {
                v0.x = gelu_exact(v0.x); v0.y = gelu_exact(v0.y);
                v1.x = gelu_exact(v1.x); v1.y = gelu_exact(v1.y);
            }
            if (HASRES) {
                float2 r0 = *(const float2*)&res[(size_t)gr * N + gc];
                float2 r1 = *(const float2*)&res[(size_t)(gr + 8) * N + gc];
                v0.x += r0.x; v0.y += r0.y;
                v1.x += r1.x; v1.y += r1.y;
            }
            *(float2*)&C[(size_t)gr * N + gc]       = v0;
            *(float2*)&C[(size_t)(gr + 8) * N + gc] = v1;
        }
    }
}

// ---------------------------------------------------------------------------
// Tensor-core flash attention v4: 2 CTAs/SM, cp.async double-buffered K/V.
// Per (b,h): BR=128 q-rows/block (8 warps x 16), BC=64 kv tile.
// smem (104KB dyn): sk[2][64][68] natural K [s][d]  (frag bank 4g+t4+8ks: CF)
//                   sv[2][64][72] natural V [s][d]  (frag bank 8t4+g: CF)
//                   pp[64][136]   Q^T staging, then P [s][m]
// K/V enter mma as raw f32 bits (HW tf32 truncation); Q/P use cvt.rna.
// One __syncthreads per kv-iter; cp.async for tile i+1 overlaps compute.
// ---------------------------------------------------------------------------
#define KST 68
#define VST 72
#define PKS 136
#define FK_WORDS (64*KST)                 // 4352
#define FV_WORDS (64*VST)                 // 4608
#define FLASH_SMEM ((2*FK_WORDS + 2*FV_WORDS + 64*PKS) * 4)   // 106496 B

__global__ void __launch_bounds__(256, 2)
flash_tc_kernel(const float* __restrict__ Q, const float* __restrict__ K,
                const float* __restrict__ V, float* __restrict__ O) {
    extern __shared__ float smf[];
    float* skb = smf;                         // 2 K stages
    float* svb = smf + 2 * FK_WORDS;          // 2 V stages
    uint32_t* pp = (uint32_t*)(smf + 2 * FK_WORDS + 2 * FV_WORDS);

    int tid  = threadIdx.x;
    int lane = tid & 31;
    int w    = tid >> 5;
    int g    = lane >> 2;
    int t4   = lane & 3;

    int bh = blockIdx.y;
    int b = bh / HEADS, h = bh % HEADS;
    int t0 = blockIdx.x * 128;
    size_t base  = (size_t)b * TSEQ * QKVN + (size_t)h * HD;
    size_t obase = (size_t)b * TSEQ * CDIM + (size_t)h * HD;

    const float scale = 0.03608439182435161f;   // 768^-0.5

    // cp.async loader mapping: row = tid>>2 (0..63), 16-float col group
    int lrow = tid >> 2;
    int lcol = (tid & 3) * 16;
    const float* Kp = K + base + (size_t)lrow * QKVN + lcol;
    const float* Vp = V + base + (size_t)lrow * QKVN + lcol;

    // issue K/V tile 0
    {
        float* sk = skb;
        float* sv = svb;
        #pragma unroll
        for (int c = 0; c < 4; c++) {
            cp16(&sk[lrow * KST + lcol + c * 4], Kp + c * 4);
            cp16(&sv[lrow * VST + lcol + c * 4], Vp + c * 4);
        }
        CP_COMMIT();
    }

    // ---- stage Q^T (pre-scaled, rounded) into pp ----
    #pragma unroll
    for (int it = 0; it < 8; it++) {
        int idx = tid + 256 * it;
        int r  = idx & 127;
        int dq = (idx >> 7) * 4;
        float4 qv = *(const float4*)&Q[base + (size_t)(t0 + r) * QKVN + dq];
        pp[(dq + 0) * PKS + r] = f2tf32(qv.x * scale);
        pp[(dq + 1) * PKS + r] = f2tf32(qv.y * scale);
        pp[(dq + 2) * PKS + r] = f2tf32(qv.z * scale);
        pp[(dq + 3) * PKS + r] = f2tf32(qv.w * scale);
    }
    __syncthreads();

    uint32_t qf[8][4];
    #pragma unroll
    for (int ks = 0; ks < 8; ks++) {
        int kb = ks * 8 + t4;
        int gm = 16 * w + g;
        qf[ks][0] = pp[kb * PKS + gm];
        qf[ks][1] = pp[kb * PKS + gm + 8];
        qf[ks][2] = pp[(kb + 4) * PKS + gm];
        qf[ks][3] = pp[(kb + 4) * PKS + gm + 8];
    }

    float o_acc[8][4];
    #pragma unroll
    for (int nt = 0; nt < 8; nt++)
        #pragma unroll
        for (int c = 0; c < 4; c++) o_acc[nt][c] = 0.f;
    float rm0 = -1e30f, rm1 = -1e30f, rl0 = 0.f, rl1 = 0.f;

    const int NKT = TSEQ / 64;
    for (int kt = 0; kt < NKT; kt++) {
        CP_WAIT(0);
        __syncthreads();   // tile kt visible; all warps done with prev iter

        // issue tile kt+1 into the other stage (overlaps compute below)
        if (kt + 1 < NKT) {
            float* sk_w = skb + ((kt + 1) & 1) * FK_WORDS;
            float* sv_w = svb + ((kt + 1) & 1) * FV_WORDS;
            size_t goff = (size_t)(kt + 1) * 64 * QKVN;
            #pragma unroll
            for (int c = 0; c < 4; c++) {
                cp16(&sk_w[lrow * KST + lcol + c * 4], Kp + goff + c * 4);
                cp16(&sv_w[lrow * VST + lcol + c * 4], Vp + goff + c * 4);
            }
        }
        CP_COMMIT();

        const uint32_t* sk = (const uint32_t*)(skb + (kt & 1) * FK_WORDS);
        const uint32_t* sv = (const uint32_t*)(svb + (kt & 1) * FV_WORDS);

        // ---- S = Q K^T  (16 x 64 per warp); B-frag = K[s=gn][d=kb] ----
        float sacc[8][4];
        #pragma unroll
        for (int nt = 0; nt < 8; nt++)
            #pragma unroll
            for (int c = 0; c < 4; c++) sacc[nt][c] = 0.f;

        #pragma unroll
        for (int ks = 0; ks < 8; ks++) {
            int kb = ks * 8 + t4;
            uint32_t bf[8][2];
            #pragma unroll
            for (int nt = 0; nt < 8; nt++) {
                int gn = nt * 8 + g;
                bf[nt][0] = sk[gn * KST + kb];
                bf[nt][1] = sk[gn * KST + kb + 4];
            }
            #pragma unroll
            for (int nt = 0; nt < 8; nt++) {
                float* d = sacc[nt];
                MMA_TF32(d, qf[ks][0], qf[ks][1], qf[ks][2], qf[ks][3],
                         bf[nt][0], bf[nt][1]);
            }
        }

        // ---- online softmax on fragments ----
        float mx0 = -1e30f, mx1 = -1e30f;
        #pragma unroll
        for (int nt = 0; nt < 8; nt++) {
            mx0 = fmaxf(mx0, fmaxf(sacc[nt][0], sacc[nt][1]));
            mx1 = fmaxf(mx1, fmaxf(sacc[nt][2], sacc[nt][3]));
        }
        mx0 = fmaxf(mx0, __shfl_xor_sync(0xffffffffu, mx0, 1));
        mx0 = fmaxf(mx0, __shfl_xor_sync(0xffffffffu, mx0, 2));
        mx1 = fmaxf(mx1, __shfl_xor_sync(0xffffffffu, mx1, 1));
        mx1 = fmaxf(mx1, __shfl_xor_sync(0xffffffffu, mx1, 2));

        float mn0 = fmaxf(rm0, mx0);
        float mn1 = fmaxf(rm1, mx1);
        float al0 = __expf(rm0 - mn0);
        float al1 = __expf(rm1 - mn1);
        rm0 = mn0; rm1 = mn1;

        int row0 = 16 * w + g;
        int row1 = row0 + 8;
        float sum0 = 0.f, sum1 = 0.f;
        #pragma unroll
        for (int nt = 0; nt < 8; nt++) {
            int col = nt * 8 + 2 * t4;
            float p0 = __expf(sacc[nt][0] - mn0);
            float p1 = __expf(sacc[nt][1] - mn0);
            float p2 = __expf(sacc[nt][2] - mn1);
            float p3 = __expf(sacc[nt][3] - mn1);
            sum0 += p0 + p1;
            sum1 += p2 + p3;
            pp[(col + 0) * PKS + row0] = f2tf32(p0);
            pp[(col + 1) * PKS + row0] = f2tf32(p1);
            pp[(col + 0) * PKS + row1] = f2tf32(p2);
            pp[(col + 1) * PKS + row1] = f2tf32(p3);
        }
        sum0 += __shfl_xor_sync(0xffffffffu, sum0, 1);
        sum0 += __shfl_xor_sync(0xffffffffu, sum0, 2);
        sum1 += __shfl_xor_sync(0xffffffffu, sum1, 1);
        sum1 += __shfl_xor_sync(0xffffffffu, sum1, 2);
        rl0 = rl0 * al0 + sum0;
        rl1 = rl1 * al1 + sum1;

        #pragma unroll
        for (int nt = 0; nt < 8; nt++) {
            o_acc[nt][0] *= al0; o_acc[nt][1] *= al0;
            o_acc[nt][2] *= al1; o_acc[nt][3] *= al1;
        }
        __syncwarp();   // P stores visible within warp (warp-private rows)

        // ---- O += P V  (A = P from pp, B = V[s=kb][d=gn]) ----
        #pragma unroll
        for (int ks = 0; ks < 8; ks++) {
            int kb = ks * 8 + t4;
            int gm = 16 * w + g;
            uint32_t af0 = pp[kb * PKS + gm];
            uint32_t af1 = pp[kb * PKS + gm + 8];
            uint32_t af2 = pp[(kb + 4) * PKS + gm];
            uint32_t af3 = pp[(kb + 4) * PKS + gm + 8];
            uint32_t bf[8][2];
            #pragma unroll
            for (int nt = 0; nt < 8; nt++) {
                int gn = nt * 8 + g;
                bf[nt][0] = sv[kb * VST + gn];
                bf[nt][1] = sv[(kb + 4) * VST + gn];
            }
            #pragma unroll
            for (int nt = 0; nt < 8; nt++) {
                float* d = o_acc[nt];
                MMA_TF32(d, af0, af1, af2, af3, bf[nt][0], bf[nt][1]);
            }
        }
    }

    // ---- epilogue: O = acc / l ----
    float inv0 = 1.f / rl0;
    float inv1 = 1.f / rl1;
    int row0 = t0 + 16 * w + g;
    int row1 = row0 + 8;
    #pragma unroll
    for (int nt = 0; nt < 8; nt++) {
        int dcol = nt * 8 + 2 * t4;
        float2 v0, v1;
        v0.x = o_acc[nt][0] * inv0; v0.y = o_acc[nt][1] * inv0;
        v1.x = o_acc[nt][2] * inv1; v1.y = o_acc[nt][3] * inv1;
        *(float2*)&O[obase + (size_t)row0 * CDIM + dcol] = v0;
        *(float2*)&O[obase + (size_t)row1 * CDIM + dcol] = v1;
    }
}

// ---------------------------------------------------------------------------
// Launch
// ---------------------------------------------------------------------------
extern "C" void kernel_launch(void* const* d_in, const int* in_sizes, int n_in,
                              void* d_out, int out_size) {
    const float* x     = (const float*)d_in[0];
    const float* Wq    = (const float*)d_in[1];
    const float* Wk    = (const float*)d_in[2];
    const float* Wv    = (const float*)d_in[3];
    const float* Wo    = (const float*)d_in[4];
    const float* bo    = (const float*)d_in[5];
    const float* ln1_g = (const float*)d_in[6];
    const float* ln1_b = (const float*)d_in[7];
    const float* ln2_g = (const float*)d_in[8];
    const float* ln2_b = (const float*)d_in[9];
    const float* W1    = (const float*)d_in[10];
    const float* b1    = (const float*)d_in[11];
    const float* W2    = (const float*)d_in[12];
    const float* b2    = (const float*)d_in[13];
    float* out = (float*)d_out;

    float *xn, *qkv, *att, *x2, *y, *hbuf, *wqkv;
    cudaGetSymbolAddress((void**)&xn,   g_xn);
    cudaGetSymbolAddress((void**)&qkv,  g_qkv);
    cudaGetSymbolAddress((void**)&att,  g_att);
    cudaGetSymbolAddress((void**)&x2,   g_x2);
    cudaGetSymbolAddress((void**)&y,    g_y);
    cudaGetSymbolAddress((void**)&hbuf, g_h);
    cudaGetSymbolAddress((void**)&wqkv, g_wqkv);

    static bool attr_done = false;
    if (!attr_done) {
        cudaFuncSetAttribute(flash_tc_kernel,
                             cudaFuncAttributeMaxDynamicSharedMemorySize,
                             FLASH_SMEM);
        cudaFuncSetAttribute(tgemm_kernel<0,0,0>,
                             cudaFuncAttributeMaxDynamicSharedMemorySize,
                             GEMM_SMEM);
        cudaFuncSetAttribute(tgemm_kernel<0,1,1>,
                             cudaFuncAttributeMaxDynamicSharedMemorySize,
                             GEMM_SMEM);
        cudaFuncSetAttribute(tgemm_kernel<1,1,0>,
                             cudaFuncAttributeMaxDynamicSharedMemorySize,
                             GEMM_SMEM);
        attr_done = true;
    }

    // 1. repack QKV weights into fused [C, 3*H*D]
    repackqkv_kernel<<<(HEADS * CDIM * HD + 255) / 256, 256>>>(Wq, Wk, Wv, wqkv);

    // 2. LN1
    ln_kernel<<<NTOK, 256>>>(x, ln1_g, ln1_b, xn);

    // 3. fused QKV projection: [8192,768] x [768,2304]
    {
        dim3 grid(QKVN / 128, NTOK / 128);
        tgemm_kernel<0,0,0><<<grid, 256, GEMM_SMEM>>>(xn, wqkv, nullptr, nullptr,
                                                      qkv, NTOK, QKVN, CDIM);
    }

    // 4. tensor-core flash attention (Q/K/V strided views into qkv)
    {
        dim3 grid(TSEQ / 128, BB * HEADS);
        flash_tc_kernel<<<grid, 256, FLASH_SMEM>>>(qkv, qkv + CDIM,
                                                   qkv + 2 * CDIM, att);
    }

    // 5. output projection + bias + residual(x) -> x2
    {
        dim3 grid(CDIM / 128, NTOK / 128);
        tgemm_kernel<0,1,1><<<grid, 256, GEMM_SMEM>>>(att, Wo, bo, x, x2,
                                                      NTOK, CDIM, CDIM);
    }

    // 6. LN2
    ln_kernel<<<NTOK, 256>>>(x2, ln2_g, ln2_b, y);

    // 7. FC1 + bias + GELU
    {
        dim3 grid(MLPD / 128, NTOK / 128);
        tgemm_kernel<1,1,0><<<grid, 256, GEMM_SMEM>>>(y, W1, b1, nullptr, hbuf,
                                                      NTOK, MLPD, CDIM);
    }

    // 8. FC2 + bias + residual(x2) -> out
    {
        dim3 grid(CDIM / 128, NTOK / 128);
        tgemm_kernel<0,1,1><<<grid, 256, GEMM_SMEM>>>(hbuf, W2, b2, x2, out,
                                                      NTOK, CDIM, MLPD);
    }
}

// round 16
// speedup vs baseline: 1.1369x; 1.0432x over previous
#include <cuda_runtime.h>
#include <math.h>
#include <stdint.h>

// Problem constants
#define BB    4
#define TSEQ  2048
#define CDIM  768
#define HEADS 12
#define HD    64
#define MLPD  3072
#define NTOK  (BB*TSEQ)          // 8192
#define QKVN  (3*CDIM)           // 2304

// ---------------------------------------------------------------------------
// Scratch (device globals; no allocation allowed)
// ---------------------------------------------------------------------------
__device__ float g_xn  [NTOK*CDIM];
__device__ float g_qkv [NTOK*QKVN];
__device__ float g_att [NTOK*CDIM];
__device__ float g_x2  [NTOK*CDIM];
__device__ float g_y   [NTOK*CDIM];
__device__ float g_h   [NTOK*MLPD];
__device__ float g_wqkv[CDIM*QKVN];

// ---------------------------------------------------------------------------
// Repack [H,C,D] x3 -> fused [C, 3*H*D]
// ---------------------------------------------------------------------------
__global__ void repackqkv_kernel(const float* __restrict__ wq,
                                 const float* __restrict__ wk,
                                 const float* __restrict__ wv,
                                 float* __restrict__ o) {
    int i = blockIdx.x * 256 + threadIdx.x;
    if (i >= HEADS * CDIM * HD) return;
    int h = i / (CDIM * HD);
    int r = i % (CDIM * HD);
    int c = r / HD;
    int d = r % HD;
    size_t base = (size_t)c * QKVN + h * HD + d;
    o[base]            = wq[i];
    o[base + CDIM]     = wk[i];
    o[base + 2*CDIM]   = wv[i];
}

// ---------------------------------------------------------------------------
// LayerNorm: one block per token row, 256 threads, C=768 -> 3 elems/thread
// ---------------------------------------------------------------------------
__global__ void ln_kernel(const float* __restrict__ x,
                          const float* __restrict__ g,
                          const float* __restrict__ b,
                          float* __restrict__ out) {
    int row = blockIdx.x;
    int tid = threadIdx.x;
    const float* xr = x + (size_t)row * CDIM;

    float v0 = xr[tid];
    float v1 = xr[tid + 256];
    float v2 = xr[tid + 512];
    float s  = v0 + v1 + v2;
    float s2 = v0*v0 + v1*v1 + v2*v2;

    #pragma unroll
    for (int o = 16; o > 0; o >>= 1) {
        s  += __shfl_xor_sync(0xffffffffu, s,  o);
        s2 += __shfl_xor_sync(0xffffffffu, s2, o);
    }
    __shared__ float rs[8], rs2[8];
    int w = tid >> 5, l = tid & 31;
    if (l == 0) { rs[w] = s; rs2[w] = s2; }
    __syncthreads();
    if (tid < 32) {
        float a  = (l < 8) ? rs[l]  : 0.f;
        float a2 = (l < 8) ? rs2[l] : 0.f;
        #pragma unroll
        for (int o = 4; o > 0; o >>= 1) {
            a  += __shfl_xor_sync(0xffffffffu, a,  o);
            a2 += __shfl_xor_sync(0xffffffffu, a2, o);
        }
        if (l == 0) { rs[0] = a; rs2[0] = a2; }
    }
    __syncthreads();
    float mu  = rs[0] * (1.f / CDIM);
    float var = rs2[0] * (1.f / CDIM) - mu * mu;
    float inv = rsqrtf(var + 1e-6f);

    float* orow = out + (size_t)row * CDIM;
    orow[tid]       = (v0 - mu) * inv * g[tid]       + b[tid];
    orow[tid + 256] = (v1 - mu) * inv * g[tid + 256] + b[tid + 256];
    orow[tid + 512] = (v2 - mu) * inv * g[tid + 512] + b[tid + 512];
}

// ---------------------------------------------------------------------------
// Common helpers
// ---------------------------------------------------------------------------
__device__ __forceinline__ float gelu_exact(float v) {
    return 0.5f * v * (1.0f + erff(v * 0.70710678118654752f));
}

__device__ __forceinline__ uint32_t f2tf32(float f) {
    uint32_t u;
    asm("cvt.rna.tf32.f32 %0, %1;" : "=r"(u) : "f"(f));
    return u;
}

#define MMA_TF32(d, a0,a1,a2,a3, b0,b1)                                      \
    asm volatile(                                                            \
        "mma.sync.aligned.m16n8k8.row.col.f32.tf32.tf32.f32 "                \
        "{%0,%1,%2,%3}, {%4,%5,%6,%7}, {%8,%9}, {%0,%1,%2,%3};"              \
        : "+f"(d[0]), "+f"(d[1]), "+f"(d[2]), "+f"(d[3])                     \
        : "r"(a0), "r"(a1), "r"(a2), "r"(a3), "r"(b0), "r"(b1))

__device__ __forceinline__ void cp16(float* dst_smem, const float* src_gmem) {
    uint32_t d = (uint32_t)__cvta_generic_to_shared(dst_smem);
    asm volatile("cp.async.cg.shared.global [%0], [%1], 16;\n"
                 :: "r"(d), "l"(src_gmem));
}
#define CP_COMMIT()  asm volatile("cp.async.commit_group;\n" ::: "memory")
#define CP_WAIT(n)   asm volatile("cp.async.wait_group %0;\n" :: "n"(n) : "memory")

// ---------------------------------------------------------------------------
// TF32 tensor-core GEMM v3: 3-stage cp.async pipeline + k-permutation.
// k-octet permutation pi(kappa)=2(kappa&3)+(kappa>>2) applied to BOTH
// operands: A-frag k-pair becomes adjacent -> uint2 loads (A LDS halved).
//   sA [128 m][40]  : v2 pair-index 4*gq+t4+4*ks  (injective per half-warp)
//   sB [32 k][132]  : scalar bank 8*t4+8*nt+gq    (bijective); +4 for row+1
// ---------------------------------------------------------------------------
#define AST 40
#define BST 132
#define STG_WORDS (128*AST + 32*BST)      // 9344 words = 37376 B
#define NSTAGE 3
#define GEMM_SMEM (NSTAGE*STG_WORDS*4)    // 112128 B

template<int ACT, int HASBIAS, int HASRES>
__global__ void __launch_bounds__(256, 2)
tgemm_kernel(const float* __restrict__ A, const float* __restrict__ B,
             const float* __restrict__ bias, const float* __restrict__ res,
             float* __restrict__ C, int M, int N, int K) {
    extern __shared__ float smg[];

    int tid  = threadIdx.x;
    int lane = tid & 31;
    int warp = tid >> 5;
    int wm = warp >> 2;
    int wn = warp & 3;
    int t4 = lane & 3;
    int gq = lane >> 2;
    int m0 = blockIdx.y * 128, n0 = blockIdx.x * 128;

    int arow = tid >> 1;
    int ap   = tid & 1;
    const float* Ap = A + (size_t)(m0 + arow) * K + ap * 16;
    int brow = tid >> 3;
    int bch  = (tid & 7) * 4;
    const float* Bp = B + (size_t)brow * N + n0 + bch;

    float acc[4][4][4];
    #pragma unroll
    for (int a = 0; a < 4; a++)
        #pragma unroll
        for (int b = 0; b < 4; b++)
            #pragma unroll
            for (int c = 0; c < 4; c++) acc[a][b][c] = 0.f;

    const int NK = K / 32;

    #pragma unroll
    for (int s = 0; s < NSTAGE - 1; s++) {
        float* sa = smg + s * STG_WORDS;
        float* sb = sa + 128 * AST;
        int k0 = s * 32;
        #pragma unroll
        for (int c = 0; c < 4; c++)
            cp16(&sa[arow * AST + ap * 16 + c * 4], Ap + k0 + c * 4);
        #pragma unroll
        for (int c = 0; c < 4; c++)
            cp16(&sb[brow * BST + bch + c * 32],
                 Bp + (size_t)k0 * N + c * 32);
        CP_COMMIT();
    }

    for (int i = 0; i < NK; i++) {
        CP_WAIT(NSTAGE - 2);
        __syncthreads();

        const uint32_t* sa = (const uint32_t*)(smg + (i % NSTAGE) * STG_WORDS);
        const uint32_t* sb = sa + 128 * AST;

        #pragma unroll
        for (int ks = 0; ks < 4; ks++) {
            int kphys = ks * 8 + 2 * t4;     // pi(t4), pi(t4+4)=+1
            uint32_t bf[4][2];
            #pragma unroll
            for (int nt = 0; nt < 4; nt++) {
                int gn = wn * 32 + nt * 8 + gq;
                bf[nt][0] = sb[kphys * BST + gn];
                bf[nt][1] = sb[(kphys + 1) * BST + gn];
            }
            uint32_t af[4][4];
            #pragma unroll
            for (int mt = 0; mt < 4; mt++) {
                int gm = wm * 64 + mt * 16 + gq;
                uint2 r0 = *(const uint2*)&sa[gm * AST + kphys];
                uint2 r1 = *(const uint2*)&sa[(gm + 8) * AST + kphys];
                af[mt][0] = r0.x;   // row g,   kappa t4
                af[mt][1] = r1.x;   // row g+8, kappa t4
                af[mt][2] = r0.y;   // row g,   kappa t4+4
                af[mt][3] = r1.y;   // row g+8, kappa t4+4
            }
            #pragma unroll
            for (int mt = 0; mt < 4; mt++)
                #pragma unroll
                for (int nt = 0; nt < 4; nt++) {
                    float* d = acc[mt][nt];
                    MMA_TF32(d, af[mt][0], af[mt][1], af[mt][2], af[mt][3],
                             bf[nt][0], bf[nt][1]);
                }
        }

        int nt_ = i + NSTAGE - 1;
        if (nt_ < NK) {
            float* sa_w = smg + (nt_ % NSTAGE) * STG_WORDS;
            float* sb_w = sa_w + 128 * AST;
            int k0 = nt_ * 32;
            #pragma unroll
            for (int c = 0; c < 4; c++)
                cp16(&sa_w[arow * AST + ap * 16 + c * 4], Ap + k0 + c * 4);
            #pragma unroll
            for (int c = 0; c < 4; c++)
                cp16(&sb_w[brow * BST + bch + c * 32],
                     Bp + (size_t)k0 * N + c * 32);
        }
        CP_COMMIT();
    }

    #pragma unroll
    for (int mt = 0; mt < 4; mt++) {
        int gr = m0 + wm * 64 + mt * 16 + gq;
        #pragma unroll
        for (int nt = 0; nt < 4; nt++) {
            int gc = n0 + wn * 32 + nt * 8 + t4 * 2;
            float2 v0, v1;
            v0.x = acc[mt][nt][0]; v0.y = acc[mt][nt][1];
            v1.x = acc[mt][nt][2]; v1.y = acc[mt][nt][3];
            if (HASBIAS) {
                float2 bb = *(const float2*)&bias[gc];
                v0.x += bb.x; v0.y += bb.y;
                v1.x += bb.x; v1.y += bb.y;
            }
            if (ACT == 1) {
                v0.x = gelu_exact(v0.x); v0.y = gelu_exact(v0.y);
                v1.x = gelu_exact(v1.x); v1.y = gelu_exact(v1.y);
            }
            if (HASRES) {
                float2 r0 = *(const float2*)&res[(size_t)gr * N + gc];
                float2 r1 = *(const float2*)&res[(size_t)(gr + 8) * N + gc];
                v0.x += r0.x; v0.y += r0.y;
                v1.x += r1.x; v1.y += r1.y;
            }
            *(float2*)&C[(size_t)gr * N + gc]       = v0;
            *(float2*)&C[(size_t)(gr + 8) * N + gc] = v1;
        }
    }
}

// ---------------------------------------------------------------------------
// Tensor-core flash attention v5: k-permutation; P never leaves registers.
// pi(kappa)=2(kappa&3)+(kappa>>2) per octet on BOTH mma phases:
//  - S phase: Q frags read from global (float2, cols 2t4/2t4+1);
//             K B-frags adjacent -> ld.shared.v2 (KST=72: CF 64-bit).
//  - PV phase: S C-frag (cols 2t4,2t4+1) IS the PV A-frag under pi ->
//             exp'ed sacc used directly as raw-bit operands. No P smem.
//  - V B-frag rows 8*oct+2t4(+1); VST=68: bank 8t4+g+8nt, CF.
// smem: 2 K stages (64x72) + 2 V stages (64x68) = 71.7KB, 2 CTAs/SM.
// ---------------------------------------------------------------------------
#define KST 72
#define VST 68
#define FK_WORDS (64*KST)                 // 4608
#define FV_WORDS (64*VST)                 // 4352
#define FLASH_SMEM ((2*FK_WORDS + 2*FV_WORDS) * 4)   // 71680 B

__global__ void __launch_bounds__(256, 2)
flash_tc_kernel(const float* __restrict__ Q, const float* __restrict__ K,
                const float* __restrict__ V, float* __restrict__ O) {
    extern __shared__ float smf[];
    float* skb = smf;                         // 2 K stages
    float* svb = smf + 2 * FK_WORDS;          // 2 V stages

    int tid  = threadIdx.x;
    int lane = tid & 31;
    int w    = tid >> 5;
    int g    = lane >> 2;
    int t4   = lane & 3;

    int bh = blockIdx.y;
    int b = bh / HEADS, h = bh % HEADS;
    int t0 = blockIdx.x * 128;
    size_t base  = (size_t)b * TSEQ * QKVN + (size_t)h * HD;
    size_t obase = (size_t)b * TSEQ * CDIM + (size_t)h * HD;

    const float scale = 0.03608439182435161f;   // 768^-0.5

    // cp.async loader mapping: row = tid>>2 (0..63), 16-float col group
    int lrow = tid >> 2;
    int lcol = (tid & 3) * 16;
    const float* Kp = K + base + (size_t)lrow * QKVN + lcol;
    const float* Vp = V + base + (size_t)lrow * QKVN + lcol;

    // issue K/V tile 0
    #pragma unroll
    for (int c = 0; c < 4; c++) {
        cp16(&skb[lrow * KST + lcol + c * 4], Kp + c * 4);
        cp16(&svb[lrow * VST + lcol + c * 4], Vp + c * 4);
    }
    CP_COMMIT();

    // ---- Q fragments straight from global (pre-scaled, rounded) ----
    // A-frag under pi: (a0,a2) = Q(row, 8ks+2t4 .. +1), (a1,a3) = row+8.
    uint32_t qf[8][4];
    {
        int row = t0 + 16 * w + g;
        const float* Qr0 = Q + base + (size_t)row * QKVN;
        const float* Qr1 = Qr0 + (size_t)8 * QKVN;
        #pragma unroll
        for (int ks = 0; ks < 8; ks++) {
            float2 q0 = *(const float2*)&Qr0[ks * 8 + 2 * t4];
            float2 q1 = *(const float2*)&Qr1[ks * 8 + 2 * t4];
            qf[ks][0] = f2tf32(q0.x * scale);
            qf[ks][2] = f2tf32(q0.y * scale);
            qf[ks][1] = f2tf32(q1.x * scale);
            qf[ks][3] = f2tf32(q1.y * scale);
        }
    }

    float o_acc[8][4];
    #pragma unroll
    for (int nt = 0; nt < 8; nt++)
        #pragma unroll
        for (int c = 0; c < 4; c++) o_acc[nt][c] = 0.f;
    float rm0 = -1e30f, rm1 = -1e30f, rl0 = 0.f, rl1 = 0.f;

    const int NKT = TSEQ / 64;
    for (int kt = 0; kt < NKT; kt++) {
        CP_WAIT(0);
        __syncthreads();   // tile kt visible; all warps done with prev iter

        if (kt + 1 < NKT) {
            float* sk_w = skb + ((kt + 1) & 1) * FK_WORDS;
            float* sv_w = svb + ((kt + 1) & 1) * FV_WORDS;
            size_t goff = (size_t)(kt + 1) * 64 * QKVN;
            #pragma unroll
            for (int c = 0; c < 4; c++) {
                cp16(&sk_w[lrow * KST + lcol + c * 4], Kp + goff + c * 4);
                cp16(&sv_w[lrow * VST + lcol + c * 4], Vp + goff + c * 4);
            }
        }
        CP_COMMIT();

        const uint32_t* sk = (const uint32_t*)(skb + (kt & 1) * FK_WORDS);
        const uint32_t* sv = (const uint32_t*)(svb + (kt & 1) * FV_WORDS);

        // ---- S = Q K^T ; K B-frags via 64-bit loads (adjacent under pi) ----
        float sacc[8][4];
        #pragma unroll
        for (int nt = 0; nt < 8; nt++)
            #pragma unroll
            for (int c = 0; c < 4; c++) sacc[nt][c] = 0.f;

        #pragma unroll
        for (int ks = 0; ks < 8; ks++) {
            int kphys = ks * 8 + 2 * t4;
            uint32_t bf[8][2];
            #pragma unroll
            for (int nt = 0; nt < 8; nt++) {
                int gn = nt * 8 + g;
                uint2 kv = *(const uint2*)&sk[gn * KST + kphys];
                bf[nt][0] = kv.x;
                bf[nt][1] = kv.y;
            }
            #pragma unroll
            for (int nt = 0; nt < 8; nt++) {
                float* d = sacc[nt];
                MMA_TF32(d, qf[ks][0], qf[ks][1], qf[ks][2], qf[ks][3],
                         bf[nt][0], bf[nt][1]);
            }
        }

        // ---- online softmax on fragments (P stays in registers) ----
        float mx0 = -1e30f, mx1 = -1e30f;
        #pragma unroll
        for (int nt = 0; nt < 8; nt++) {
            mx0 = fmaxf(mx0, fmaxf(sacc[nt][0], sacc[nt][1]));
            mx1 = fmaxf(mx1, fmaxf(sacc[nt][2], sacc[nt][3]));
        }
        mx0 = fmaxf(mx0, __shfl_xor_sync(0xffffffffu, mx0, 1));
        mx0 = fmaxf(mx0, __shfl_xor_sync(0xffffffffu, mx0, 2));
        mx1 = fmaxf(mx1, __shfl_xor_sync(0xffffffffu, mx1, 1));
        mx1 = fmaxf(mx1, __shfl_xor_sync(0xffffffffu, mx1, 2));

        float mn0 = fmaxf(rm0, mx0);
        float mn1 = fmaxf(rm1, mx1);
        float al0 = __expf(rm0 - mn0);
        float al1 = __expf(rm1 - mn1);
        rm0 = mn0; rm1 = mn1;

        float sum0 = 0.f, sum1 = 0.f;
        #pragma unroll
        for (int nt = 0; nt < 8; nt++) {
            sacc[nt][0] = __expf(sacc[nt][0] - mn0);
            sacc[nt][1] = __expf(sacc[nt][1] - mn0);
            sacc[nt][2] = __expf(sacc[nt][2] - mn1);
            sacc[nt][3] = __expf(sacc[nt][3] - mn1);
            sum0 += sacc[nt][0] + sacc[nt][1];
            sum1 += sacc[nt][2] + sacc[nt][3];
        }
        sum0 += __shfl_xor_sync(0xffffffffu, sum0, 1);
        sum0 += __shfl_xor_sync(0xffffffffu, sum0, 2);
        sum1 += __shfl_xor_sync(0xffffffffu, sum1, 1);
        sum1 += __shfl_xor_sync(0xffffffffu, sum1, 2);
        rl0 = rl0 * al0 + sum0;
        rl1 = rl1 * al1 + sum1;

        #pragma unroll
        for (int nt = 0; nt < 8; nt++) {
            o_acc[nt][0] *= al0; o_acc[nt][1] *= al0;
            o_acc[nt][2] *= al1; o_acc[nt][3] *= al1;
        }

        // ---- O += P V : A-frag = exp'ed sacc[oct] (pi makes layouts match)
        //      a0 = P(g, 2t4) = sacc[oct][0], a1 = P(g+8, 2t4) = sacc[oct][2]
        //      a2 = P(g, 2t4+1) = sacc[oct][1], a3 = sacc[oct][3]
        #pragma unroll
        for (int oct = 0; oct < 8; oct++) {
            uint32_t af0 = __float_as_uint(sacc[oct][0]);
            uint32_t af1 = __float_as_uint(sacc[oct][2]);
            uint32_t af2 = __float_as_uint(sacc[oct][1]);
            uint32_t af3 = __float_as_uint(sacc[oct][3]);
            int srow = oct * 8 + 2 * t4;        // pi(t4); +1 = pi(t4+4)
            uint32_t bf[8][2];
            #pragma unroll
            for (int nt = 0; nt < 8; nt++) {
                int gn = nt * 8 + g;
                bf[nt][0] = sv[srow * VST + gn];
                bf[nt][1] = sv[(srow + 1) * VST + gn];
            }
            #pragma unroll
            for (int nt = 0; nt < 8; nt++) {
                float* d = o_acc[nt];
                MMA_TF32(d, af0, af1, af2, af3, bf[nt][0], bf[nt][1]);
            }
        }
    }

    // ---- epilogue: O = acc / l ----
    float inv0 = 1.f / rl0;
    float inv1 = 1.f / rl1;
    int row0 = t0 + 16 * w + g;
    int row1 = row0 + 8;
    #pragma unroll
    for (int nt = 0; nt < 8; nt++) {
        int dcol = nt * 8 + 2 * t4;
        float2 v0, v1;
        v0.x = o_acc[nt][0] * inv0; v0.y = o_acc[nt][1] * inv0;
        v1.x = o_acc[nt][2] * inv1; v1.y = o_acc[nt][3] * inv1;
        *(float2*)&O[obase + (size_t)row0 * CDIM + dcol] = v0;
        *(float2*)&O[obase + (size_t)row1 * CDIM + dcol] = v1;
    }
}

// ---------------------------------------------------------------------------
// Launch
// ---------------------------------------------------------------------------
extern "C" void kernel_launch(void* const* d_in, const int* in_sizes, int n_in,
                              void* d_out, int out_size) {
    const float* x     = (const float*)d_in[0];
    const float* Wq    = (const float*)d_in[1];
    const float* Wk    = (const float*)d_in[2];
    const float* Wv    = (const float*)d_in[3];
    const float* Wo    = (const float*)d_in[4];
    const float* bo    = (const float*)d_in[5];
    const float* ln1_g = (const float*)d_in[6];
    const float* ln1_b = (const float*)d_in[7];
    const float* ln2_g = (const float*)d_in[8];
    const float* ln2_b = (const float*)d_in[9];
    const float* W1    = (const float*)d_in[10];
    const float* b1    = (const float*)d_in[11];
    const float* W2    = (const float*)d_in[12];
    const float* b2    = (const float*)d_in[13];
    float* out = (float*)d_out;

    float *xn, *qkv, *att, *x2, *y, *hbuf, *wqkv;
    cudaGetSymbolAddress((void**)&xn,   g_xn);
    cudaGetSymbolAddress((void**)&qkv,  g_qkv);
    cudaGetSymbolAddress((void**)&att,  g_att);
    cudaGetSymbolAddress((void**)&x2,   g_x2);
    cudaGetSymbolAddress((void**)&y,    g_y);
    cudaGetSymbolAddress((void**)&hbuf, g_h);
    cudaGetSymbolAddress((void**)&wqkv, g_wqkv);

    static bool attr_done = false;
    if (!attr_done) {
        cudaFuncSetAttribute(flash_tc_kernel,
                             cudaFuncAttributeMaxDynamicSharedMemorySize,
                             FLASH_SMEM);
        cudaFuncSetAttribute(tgemm_kernel<0,0,0>,
                             cudaFuncAttributeMaxDynamicSharedMemorySize,
                             GEMM_SMEM);
        cudaFuncSetAttribute(tgemm_kernel<0,1,1>,
                             cudaFuncAttributeMaxDynamicSharedMemorySize,
                             GEMM_SMEM);
        cudaFuncSetAttribute(tgemm_kernel<1,1,0>,
                             cudaFuncAttributeMaxDynamicSharedMemorySize,
                             GEMM_SMEM);
        attr_done = true;
    }

    // 1. repack QKV weights into fused [C, 3*H*D]
    repackqkv_kernel<<<(HEADS * CDIM * HD + 255) / 256, 256>>>(Wq, Wk, Wv, wqkv);

    // 2. LN1
    ln_kernel<<<NTOK, 256>>>(x, ln1_g, ln1_b, xn);

    // 3. fused QKV projection: [8192,768] x [768,2304]
    {
        dim3 grid(QKVN / 128, NTOK / 128);
        tgemm_kernel<0,0,0><<<grid, 256, GEMM_SMEM>>>(xn, wqkv, nullptr, nullptr,
                                                      qkv, NTOK, QKVN, CDIM);
    }

    // 4. tensor-core flash attention (Q/K/V strided views into qkv)
    {
        dim3 grid(TSEQ / 128, BB * HEADS);
        flash_tc_kernel<<<grid, 256, FLASH_SMEM>>>(qkv, qkv + CDIM,
                                                   qkv + 2 * CDIM, att);
    }

    // 5. output projection + bias + residual(x) -> x2
    {
        dim3 grid(CDIM / 128, NTOK / 128);
        tgemm_kernel<0,1,1><<<grid, 256, GEMM_SMEM>>>(att, Wo, bo, x, x2,
                                                      NTOK, CDIM, CDIM);
    }

    // 6. LN2
    ln_kernel<<<NTOK, 256>>>(x2, ln2_g, ln2_b, y);

    // 7. FC1 + bias + GELU
    {
        dim3 grid(MLPD / 128, NTOK / 128);
        tgemm_kernel<1,1,0><<<grid, 256, GEMM_SMEM>>>(y, W1, b1, nullptr, hbuf,
                                                      NTOK, MLPD, CDIM);
    }

    // 8. FC2 + bias + residual(x2) -> out
    {
        dim3 grid(CDIM / 128, NTOK / 128);
        tgemm_kernel<0,1,1><<<grid, 256, GEMM_SMEM>>>(hbuf, W2, b2, x2, out,
                                                      NTOK, CDIM, MLPD);
    }
}